// round 1
// baseline (speedup 1.0000x reference)
#include <cuda_runtime.h>

#define BB   16
#define CIN  512
#define HH   40
#define WW   40
#define HW   1600
#define NTOK 80
#define CG   512
#define EE   256
#define COUT 512
#define NH   8
#define HC   32
#define BN_EPS 1e-3f

// scratch (device globals; no allocation allowed)
__device__ float g_buf[BB * NTOK * EE];     // [b][n][e]   1.3 MB
__device__ float e_buf[(size_t)BB * HW * EE];// [b][hw][e] 26.2 MB
__device__ float attn_buf[BB * NH * HW];    // [b][m][hw] 0.8 MB

// ---------------- Kernel 1: guide FC  g = guide @ Wg^T + bg ----------------
__global__ void guide_gemm(const float* __restrict__ guide,
                           const float* __restrict__ Wg,
                           const float* __restrict__ bg) {
    __shared__ float As[32][33];
    __shared__ float Bs[32][33];
    int tid  = threadIdx.x;
    int row0 = blockIdx.x * 32;   // over B*N = 1280
    int col0 = blockIdx.y * 32;   // over E = 256
    int tx = tid & 31, ty = tid >> 5;
    float acc[4] = {0.f, 0.f, 0.f, 0.f};
    for (int kc = 0; kc < CG; kc += 32) {
        int r = tid >> 3, kq = (tid & 7) * 4;
        float4 a4 = *reinterpret_cast<const float4*>(&guide[(size_t)(row0 + r) * CG + kc + kq]);
        As[r][kq] = a4.x; As[r][kq + 1] = a4.y; As[r][kq + 2] = a4.z; As[r][kq + 3] = a4.w;
        float4 b4 = *reinterpret_cast<const float4*>(&Wg[(size_t)(col0 + r) * CG + kc + kq]);
        Bs[r][kq] = b4.x; Bs[r][kq + 1] = b4.y; Bs[r][kq + 2] = b4.z; Bs[r][kq + 3] = b4.w;
        __syncthreads();
        #pragma unroll
        for (int k = 0; k < 32; k++) {
            float bv = Bs[tx][k];
            #pragma unroll
            for (int rr = 0; rr < 4; rr++)
                acc[rr] += As[ty + 8 * rr][k] * bv;
        }
        __syncthreads();
    }
    float bias = bg[col0 + tx];
    #pragma unroll
    for (int rr = 0; rr < 4; rr++)
        g_buf[(size_t)(row0 + ty + 8 * rr) * EE + col0 + tx] = acc[rr] + bias;
}

// -------- Kernel 2: embed 1x1 conv + BN, output layout [b][hw][e] ----------
__global__ void embed_gemm(const float* __restrict__ x,
                           const float* __restrict__ We,
                           const float* __restrict__ gamma_e,
                           const float* __restrict__ beta_e) {
    __shared__ __align__(16) float xs[16 * 64];
    __shared__ __align__(16) float ws[16 * 68];
    int tid = threadIdx.x;
    int hw0 = blockIdx.x * 64;
    int e0  = blockIdx.y * 64;
    int b   = blockIdx.z;
    int tx = tid & 15, ty = tid >> 4;
    float acc[4][4] = {};
    const float* xb = x + (size_t)b * CIN * HW;
    for (int kc = 0; kc < CIN; kc += 16) {
        {
            int kk = tid >> 4, h0 = (tid & 15) * 4;
            float4 v = *reinterpret_cast<const float4*>(&xb[(size_t)(kc + kk) * HW + hw0 + h0]);
            *reinterpret_cast<float4*>(&xs[kk * 64 + h0]) = v;
            int el = tid >> 2, kq = (tid & 3) * 4;
            float4 wv = *reinterpret_cast<const float4*>(&We[(size_t)(e0 + el) * CIN + kc + kq]);
            ws[(kq + 0) * 68 + el] = wv.x;
            ws[(kq + 1) * 68 + el] = wv.y;
            ws[(kq + 2) * 68 + el] = wv.z;
            ws[(kq + 3) * 68 + el] = wv.w;
        }
        __syncthreads();
        #pragma unroll
        for (int kk = 0; kk < 16; kk++) {
            float4 av = *reinterpret_cast<const float4*>(&xs[kk * 64 + ty * 4]);
            float4 bv = *reinterpret_cast<const float4*>(&ws[kk * 68 + tx * 4]);
            float a[4] = {av.x, av.y, av.z, av.w};
            float bw[4] = {bv.x, bv.y, bv.z, bv.w};
            #pragma unroll
            for (int i = 0; i < 4; i++)
                #pragma unroll
                for (int j = 0; j < 4; j++)
                    acc[i][j] += a[i] * bw[j];
        }
        __syncthreads();
    }
    int e = e0 + tx * 4;
    float sc[4], bt[4];
    #pragma unroll
    for (int j = 0; j < 4; j++) {
        sc[j] = gamma_e[e + j] * rsqrtf(1.0f + BN_EPS);
        bt[j] = beta_e[e + j];
    }
    #pragma unroll
    for (int i = 0; i < 4; i++) {
        int hw = hw0 + ty * 4 + i;
        float4 o;
        o.x = acc[i][0] * sc[0] + bt[0];
        o.y = acc[i][1] * sc[1] + bt[1];
        o.z = acc[i][2] * sc[2] + bt[2];
        o.w = acc[i][3] * sc[3] + bt[3];
        *reinterpret_cast<float4*>(&e_buf[((size_t)b * HW + hw) * EE + e]) = o;
    }
}

// -------- Kernel 3: attn = sigmoid(max_n <e, g>/sqrt(C) + head_bias) -------
__global__ void attn_kernel(const float* __restrict__ head_bias) {
    __shared__ __align__(16) float gs[NTOK * HC];
    int tid = threadIdx.x;
    int hw0 = blockIdx.x * 128;
    int m   = blockIdx.y;
    int b   = blockIdx.z;
    for (int idx = tid; idx < NTOK * HC; idx += 128) {
        int n = idx >> 5, c = idx & 31;
        gs[idx] = g_buf[((size_t)(b * NTOK + n)) * EE + m * HC + c];
    }
    __syncthreads();
    int hw = hw0 + tid;
    if (hw >= HW) return;
    float4 ev[8];
    const float* ep = &e_buf[((size_t)b * HW + hw) * EE + m * HC];
    #pragma unroll
    for (int j = 0; j < 8; j++) ev[j] = reinterpret_cast<const float4*>(ep)[j];
    float maxv = -3.4e38f;
    for (int n = 0; n < NTOK; n++) {
        const float4* gp = reinterpret_cast<const float4*>(&gs[n * HC]);
        float acc = 0.f;
        #pragma unroll
        for (int j = 0; j < 8; j++) {
            float4 g4 = gp[j];
            acc += ev[j].x * g4.x + ev[j].y * g4.y + ev[j].z * g4.z + ev[j].w * g4.w;
        }
        maxv = fmaxf(maxv, acc);
    }
    float a = maxv * 0.17677669529663687f + head_bias[m]; // 1/sqrt(32)
    float s = 1.0f / (1.0f + expf(-a));
    attn_buf[(size_t)(b * NH + m) * HW + hw] = s;
}

// ---- Kernel 4: 3x3 conv + BN + per-head gate (f32x2 packed inner loop) ----
// block: (co_tile=64 == one head) x (4 rows x 40 cols), 256 threads
// thread: 8 co (4 f32x2 pairs) x 5 px
__global__ void __launch_bounds__(256, 2) conv3x3_gated(
        const float* __restrict__ x,
        const float* __restrict__ Wp,
        const float* __restrict__ gamma_p,
        const float* __restrict__ beta_p,
        float* __restrict__ out) {
    __shared__ __align__(16) float xs[8 * 6 * 44];   // [ci][row 6][col 44(pad)]
    __shared__ __align__(16) float ws[8 * 9 * 64];   // [ci*9+k][co]
    int tid = threadIdx.x;
    int co_base = blockIdx.x * 64;
    int h0 = blockIdx.y * 4;
    int b  = blockIdx.z;
    int cg = tid >> 5;        // co sub-block of 8
    int pg = tid & 31;
    int r  = pg >> 3;         // 0..3
    int w0 = (pg & 7) * 5;    // 0..35

    unsigned long long acc2[4][5];
    #pragma unroll
    for (int j = 0; j < 4; j++)
        #pragma unroll
        for (int p = 0; p < 5; p++) acc2[j][p] = 0ULL;

    const float* xb = x + (size_t)b * CIN * HW;

    for (int cc = 0; cc < CIN; cc += 8) {
        // stage x tile [8ci][6 rows][42 cols] with zero halo
        for (int idx = tid; idx < 8 * 6 * 42; idx += 256) {
            int ci  = idx / 252;
            int rem = idx % 252;
            int rr  = rem / 42;
            int wc  = rem % 42;
            int h = h0 - 1 + rr;
            int w = wc - 1;
            float v = 0.f;
            if (h >= 0 && h < HH && w >= 0 && w < WW)
                v = xb[(size_t)(cc + ci) * HW + h * WW + w];
            xs[(ci * 6 + rr) * 44 + wc] = v;
        }
        // stage weights: ws[rem*64 + lco], rem = ci*9+k (contiguous in GMEM per co)
        for (int idx = tid; idx < 8 * 9 * 64; idx += 256) {
            int lco = idx / 72;
            int rem = idx % 72;
            ws[rem * 64 + lco] = Wp[(size_t)(co_base + lco) * (CIN * 9) + cc * 9 + rem];
        }
        __syncthreads();
        #pragma unroll
        for (int ci = 0; ci < 8; ci++) {
            #pragma unroll
            for (int kh = 0; kh < 3; kh++) {
                unsigned long long xx2[7];
                const float* xrow = &xs[(ci * 6 + r + kh) * 44 + w0];
                #pragma unroll
                for (int t = 0; t < 7; t++) {
                    float v = xrow[t];
                    asm("mov.b64 %0, {%1, %2};" : "=l"(xx2[t]) : "f"(v), "f"(v));
                }
                #pragma unroll
                for (int kw = 0; kw < 3; kw++) {
                    const float* wrow = &ws[(ci * 9 + kh * 3 + kw) * 64 + cg * 8];
                    unsigned long long w2[4];
                    #pragma unroll
                    for (int j = 0; j < 4; j++)
                        w2[j] = *reinterpret_cast<const unsigned long long*>(wrow + 2 * j);
                    #pragma unroll
                    for (int j = 0; j < 4; j++)
                        #pragma unroll
                        for (int p = 0; p < 5; p++)
                            asm("fma.rn.f32x2 %0, %1, %2, %0;"
                                : "+l"(acc2[j][p]) : "l"(w2[j]), "l"(xx2[kw + p]));
                }
            }
        }
        __syncthreads();
    }

    // epilogue: BN + per-head sigmoid gate
    int m = co_base >> 6;  // 64 channels per head, co tile == head
    float av[5];
    #pragma unroll
    for (int p = 0; p < 5; p++)
        av[p] = attn_buf[(size_t)(b * NH + m) * HW + (h0 + r) * WW + w0 + p];
    float inv = rsqrtf(1.0f + BN_EPS);
    #pragma unroll
    for (int j = 0; j < 4; j++) {
        int co = co_base + cg * 8 + 2 * j;
        float sc0 = gamma_p[co] * inv;
        float sc1 = gamma_p[co + 1] * inv;
        float bt0 = beta_p[co], bt1 = beta_p[co + 1];
        #pragma unroll
        for (int p = 0; p < 5; p++) {
            float lo, hi;
            asm("mov.b64 {%0, %1}, %2;" : "=f"(lo), "=f"(hi) : "l"(acc2[j][p]));
            int hw = (h0 + r) * WW + w0 + p;
            out[((size_t)(b * COUT + co)) * HW + hw]     = (lo * sc0 + bt0) * av[p];
            out[((size_t)(b * COUT + co + 1)) * HW + hw] = (hi * sc1 + bt1) * av[p];
        }
    }
}

extern "C" void kernel_launch(void* const* d_in, const int* in_sizes, int n_in,
                              void* d_out, int out_size) {
    const float* x         = (const float*)d_in[0];
    const float* guide     = (const float*)d_in[1];
    const float* We        = (const float*)d_in[2];
    const float* gamma_e   = (const float*)d_in[3];
    const float* beta_e    = (const float*)d_in[4];
    const float* Wg        = (const float*)d_in[5];
    const float* bg        = (const float*)d_in[6];
    const float* head_bias = (const float*)d_in[7];
    const float* Wp        = (const float*)d_in[8];
    const float* gamma_p   = (const float*)d_in[9];
    const float* beta_p    = (const float*)d_in[10];
    float* out = (float*)d_out;

    guide_gemm<<<dim3(40, 8), 256>>>(guide, Wg, bg);
    embed_gemm<<<dim3(25, 4, 16), 256>>>(x, We, gamma_e, beta_e);
    attn_kernel<<<dim3(13, 8, 16), 128>>>(head_bias);
    conv3x3_gated<<<dim3(8, 10, 16), 256>>>(x, Wp, gamma_p, beta_p, out);
}

// round 2
// speedup vs baseline: 1.0005x; 1.0005x over previous
#include <cuda_runtime.h>

#define BB   16
#define CIN  512
#define HH   40
#define WW   40
#define HW   1600
#define NTOK 80
#define CG   512
#define EE   256
#define COUT 512
#define NH   8
#define HC   32
#define BN_EPS 1e-3f

// scratch (device globals; no allocation allowed)
__device__ float g_buf[BB * NTOK * EE];     // [b][n][e]   1.3 MB
__device__ float e_buf[(size_t)BB * HW * EE];// [b][hw][e] 26.2 MB
__device__ float attn_buf[BB * NH * HW];    // [b][m][hw] 0.8 MB

// ---------------- Kernel 1: guide FC  g = guide @ Wg^T + bg ----------------
__global__ void guide_gemm(const float* __restrict__ guide,
                           const float* __restrict__ Wg,
                           const float* __restrict__ bg) {
    __shared__ float As[32][33];
    __shared__ float Bs[32][33];
    int tid  = threadIdx.x;
    int row0 = blockIdx.x * 32;   // over B*N = 1280
    int col0 = blockIdx.y * 32;   // over E = 256
    int tx = tid & 31, ty = tid >> 5;
    float acc[4] = {0.f, 0.f, 0.f, 0.f};
    for (int kc = 0; kc < CG; kc += 32) {
        int r = tid >> 3, kq = (tid & 7) * 4;
        float4 a4 = *reinterpret_cast<const float4*>(&guide[(size_t)(row0 + r) * CG + kc + kq]);
        As[r][kq] = a4.x; As[r][kq + 1] = a4.y; As[r][kq + 2] = a4.z; As[r][kq + 3] = a4.w;
        float4 b4 = *reinterpret_cast<const float4*>(&Wg[(size_t)(col0 + r) * CG + kc + kq]);
        Bs[r][kq] = b4.x; Bs[r][kq + 1] = b4.y; Bs[r][kq + 2] = b4.z; Bs[r][kq + 3] = b4.w;
        __syncthreads();
        #pragma unroll
        for (int k = 0; k < 32; k++) {
            float bv = Bs[tx][k];
            #pragma unroll
            for (int rr = 0; rr < 4; rr++)
                acc[rr] += As[ty + 8 * rr][k] * bv;
        }
        __syncthreads();
    }
    float bias = bg[col0 + tx];
    #pragma unroll
    for (int rr = 0; rr < 4; rr++)
        g_buf[(size_t)(row0 + ty + 8 * rr) * EE + col0 + tx] = acc[rr] + bias;
}

// -------- Kernel 2: embed 1x1 conv + BN, output layout [b][hw][e] ----------
__global__ void embed_gemm(const float* __restrict__ x,
                           const float* __restrict__ We,
                           const float* __restrict__ gamma_e,
                           const float* __restrict__ beta_e) {
    __shared__ __align__(16) float xs[16 * 64];
    __shared__ __align__(16) float ws[16 * 68];
    int tid = threadIdx.x;
    int hw0 = blockIdx.x * 64;
    int e0  = blockIdx.y * 64;
    int b   = blockIdx.z;
    int tx = tid & 15, ty = tid >> 4;
    float acc[4][4] = {};
    const float* xb = x + (size_t)b * CIN * HW;
    for (int kc = 0; kc < CIN; kc += 16) {
        {
            int kk = tid >> 4, h0 = (tid & 15) * 4;
            float4 v = *reinterpret_cast<const float4*>(&xb[(size_t)(kc + kk) * HW + hw0 + h0]);
            *reinterpret_cast<float4*>(&xs[kk * 64 + h0]) = v;
            int el = tid >> 2, kq = (tid & 3) * 4;
            float4 wv = *reinterpret_cast<const float4*>(&We[(size_t)(e0 + el) * CIN + kc + kq]);
            ws[(kq + 0) * 68 + el] = wv.x;
            ws[(kq + 1) * 68 + el] = wv.y;
            ws[(kq + 2) * 68 + el] = wv.z;
            ws[(kq + 3) * 68 + el] = wv.w;
        }
        __syncthreads();
        #pragma unroll
        for (int kk = 0; kk < 16; kk++) {
            float4 av = *reinterpret_cast<const float4*>(&xs[kk * 64 + ty * 4]);
            float4 bv = *reinterpret_cast<const float4*>(&ws[kk * 68 + tx * 4]);
            float a[4] = {av.x, av.y, av.z, av.w};
            float bw[4] = {bv.x, bv.y, bv.z, bv.w};
            #pragma unroll
            for (int i = 0; i < 4; i++)
                #pragma unroll
                for (int j = 0; j < 4; j++)
                    acc[i][j] += a[i] * bw[j];
        }
        __syncthreads();
    }
    int e = e0 + tx * 4;
    float sc[4], bt[4];
    #pragma unroll
    for (int j = 0; j < 4; j++) {
        sc[j] = gamma_e[e + j] * rsqrtf(1.0f + BN_EPS);
        bt[j] = beta_e[e + j];
    }
    #pragma unroll
    for (int i = 0; i < 4; i++) {
        int hw = hw0 + ty * 4 + i;
        float4 o;
        o.x = acc[i][0] * sc[0] + bt[0];
        o.y = acc[i][1] * sc[1] + bt[1];
        o.z = acc[i][2] * sc[2] + bt[2];
        o.w = acc[i][3] * sc[3] + bt[3];
        *reinterpret_cast<float4*>(&e_buf[((size_t)b * HW + hw) * EE + e]) = o;
    }
}

// -------- Kernel 3: attn = sigmoid(max_n <e, g>/sqrt(C) + head_bias) -------
__global__ void attn_kernel(const float* __restrict__ head_bias) {
    __shared__ __align__(16) float gs[NTOK * HC];
    int tid = threadIdx.x;
    int hw0 = blockIdx.x * 128;
    int m   = blockIdx.y;
    int b   = blockIdx.z;
    for (int idx = tid; idx < NTOK * HC; idx += 128) {
        int n = idx >> 5, c = idx & 31;
        gs[idx] = g_buf[((size_t)(b * NTOK + n)) * EE + m * HC + c];
    }
    __syncthreads();
    int hw = hw0 + tid;
    if (hw >= HW) return;
    float4 ev[8];
    const float* ep = &e_buf[((size_t)b * HW + hw) * EE + m * HC];
    #pragma unroll
    for (int j = 0; j < 8; j++) ev[j] = reinterpret_cast<const float4*>(ep)[j];
    float maxv = -3.4e38f;
    for (int n = 0; n < NTOK; n++) {
        const float4* gp = reinterpret_cast<const float4*>(&gs[n * HC]);
        float acc = 0.f;
        #pragma unroll
        for (int j = 0; j < 8; j++) {
            float4 g4 = gp[j];
            acc += ev[j].x * g4.x + ev[j].y * g4.y + ev[j].z * g4.z + ev[j].w * g4.w;
        }
        maxv = fmaxf(maxv, acc);
    }
    float a = maxv * 0.17677669529663687f + head_bias[m]; // 1/sqrt(32)
    float s = 1.0f / (1.0f + expf(-a));
    attn_buf[(size_t)(b * NH + m) * HW + hw] = s;
}

// ---- Kernel 4: 3x3 conv + BN + per-head gate (f32x2 packed inner loop) ----
// block: (co_tile=64 == one head) x (4 rows x 40 cols), 256 threads
// thread: 8 co (4 f32x2 pairs) x 5 px
__global__ void __launch_bounds__(256, 2) conv3x3_gated(
        const float* __restrict__ x,
        const float* __restrict__ Wp,
        const float* __restrict__ gamma_p,
        const float* __restrict__ beta_p,
        float* __restrict__ out) {
    __shared__ __align__(16) float xs[8 * 6 * 44];   // [ci][row 6][col 44(pad)]
    __shared__ __align__(16) float ws[8 * 9 * 64];   // [ci*9+k][co]
    int tid = threadIdx.x;
    int co_base = blockIdx.x * 64;
    int h0 = blockIdx.y * 4;
    int b  = blockIdx.z;
    int cg = tid >> 5;        // co sub-block of 8
    int pg = tid & 31;
    int r  = pg >> 3;         // 0..3
    int w0 = (pg & 7) * 5;    // 0..35

    unsigned long long acc2[4][5];
    #pragma unroll
    for (int j = 0; j < 4; j++)
        #pragma unroll
        for (int p = 0; p < 5; p++) acc2[j][p] = 0ULL;

    const float* xb = x + (size_t)b * CIN * HW;

    for (int cc = 0; cc < CIN; cc += 8) {
        // stage x tile [8ci][6 rows][42 cols] with zero halo
        for (int idx = tid; idx < 8 * 6 * 42; idx += 256) {
            int ci  = idx / 252;
            int rem = idx % 252;
            int rr  = rem / 42;
            int wc  = rem % 42;
            int h = h0 - 1 + rr;
            int w = wc - 1;
            float v = 0.f;
            if (h >= 0 && h < HH && w >= 0 && w < WW)
                v = xb[(size_t)(cc + ci) * HW + h * WW + w];
            xs[(ci * 6 + rr) * 44 + wc] = v;
        }
        // stage weights: ws[rem*64 + lco], rem = ci*9+k (contiguous in GMEM per co)
        for (int idx = tid; idx < 8 * 9 * 64; idx += 256) {
            int lco = idx / 72;
            int rem = idx % 72;
            ws[rem * 64 + lco] = Wp[(size_t)(co_base + lco) * (CIN * 9) + cc * 9 + rem];
        }
        __syncthreads();
        #pragma unroll
        for (int ci = 0; ci < 8; ci++) {
            #pragma unroll
            for (int kh = 0; kh < 3; kh++) {
                unsigned long long xx2[7];
                const float* xrow = &xs[(ci * 6 + r + kh) * 44 + w0];
                #pragma unroll
                for (int t = 0; t < 7; t++) {
                    float v = xrow[t];
                    asm("mov.b64 %0, {%1, %2};" : "=l"(xx2[t]) : "f"(v), "f"(v));
                }
                #pragma unroll
                for (int kw = 0; kw < 3; kw++) {
                    const float* wrow = &ws[(ci * 9 + kh * 3 + kw) * 64 + cg * 8];
                    unsigned long long w2[4];
                    #pragma unroll
                    for (int j = 0; j < 4; j++)
                        w2[j] = *reinterpret_cast<const unsigned long long*>(wrow + 2 * j);
                    #pragma unroll
                    for (int j = 0; j < 4; j++)
                        #pragma unroll
                        for (int p = 0; p < 5; p++)
                            asm("fma.rn.f32x2 %0, %1, %2, %0;"
                                : "+l"(acc2[j][p]) : "l"(w2[j]), "l"(xx2[kw + p]));
                }
            }
        }
        __syncthreads();
    }

    // epilogue: BN + per-head sigmoid gate
    int m = co_base >> 6;  // 64 channels per head, co tile == head
    float av[5];
    #pragma unroll
    for (int p = 0; p < 5; p++)
        av[p] = attn_buf[(size_t)(b * NH + m) * HW + (h0 + r) * WW + w0 + p];
    float inv = rsqrtf(1.0f + BN_EPS);
    #pragma unroll
    for (int j = 0; j < 4; j++) {
        int co = co_base + cg * 8 + 2 * j;
        float sc0 = gamma_p[co] * inv;
        float sc1 = gamma_p[co + 1] * inv;
        float bt0 = beta_p[co], bt1 = beta_p[co + 1];
        #pragma unroll
        for (int p = 0; p < 5; p++) {
            float lo, hi;
            asm("mov.b64 {%0, %1}, %2;" : "=f"(lo), "=f"(hi) : "l"(acc2[j][p]));
            int hw = (h0 + r) * WW + w0 + p;
            out[((size_t)(b * COUT + co)) * HW + hw]     = (lo * sc0 + bt0) * av[p];
            out[((size_t)(b * COUT + co + 1)) * HW + hw] = (hi * sc1 + bt1) * av[p];
        }
    }
}

extern "C" void kernel_launch(void* const* d_in, const int* in_sizes, int n_in,
                              void* d_out, int out_size) {
    const float* x         = (const float*)d_in[0];
    const float* guide     = (const float*)d_in[1];
    const float* We        = (const float*)d_in[2];
    const float* gamma_e   = (const float*)d_in[3];
    const float* beta_e    = (const float*)d_in[4];
    const float* Wg        = (const float*)d_in[5];
    const float* bg        = (const float*)d_in[6];
    const float* head_bias = (const float*)d_in[7];
    const float* Wp        = (const float*)d_in[8];
    const float* gamma_p   = (const float*)d_in[9];
    const float* beta_p    = (const float*)d_in[10];
    float* out = (float*)d_out;

    guide_gemm<<<dim3(40, 8), 256>>>(guide, Wg, bg);
    embed_gemm<<<dim3(25, 4, 16), 256>>>(x, We, gamma_e, beta_e);
    attn_kernel<<<dim3(13, 8, 16), 128>>>(head_bias);
    conv3x3_gated<<<dim3(8, 10, 16), 256>>>(x, Wp, gamma_p, beta_p, out);
}

// round 4
// speedup vs baseline: 2.9032x; 2.9018x over previous
#include <cuda_runtime.h>
#include <cuda_bf16.h>
#include <cstdint>

#define BB   16
#define CIN  512
#define HH   40
#define WW   40
#define HW   1600
#define NTOK 80
#define CG   512
#define EE   256
#define COUT 512
#define NH   8
#define HC   32
#define BN_EPS 1e-3f
#define PPAD 1920   // 48 padded rows x 40 cols per image

// ------------------------------ scratch (device globals) -------------------
__device__ float g_buf[BB * NTOK * EE];
__device__ float e_buf[(size_t)BB * HW * EE];
__device__ float attn_buf[BB * NH * HW];
__device__ __align__(256) __nv_bfloat16 xsh_hi[(size_t)3 * BB * PPAD * CIN];
__device__ __align__(256) __nv_bfloat16 xsh_lo[(size_t)3 * BB * PPAD * CIN];
__device__ __align__(256) __nv_bfloat16 wk_hi[(size_t)9 * COUT * CIN];
__device__ __align__(256) __nv_bfloat16 wk_lo[(size_t)9 * COUT * CIN];

// ------------------------------ helpers ------------------------------------
__device__ __forceinline__ uint32_t smem_u32(const void* p) {
    uint32_t a;
    asm("{ .reg .u64 t; cvta.to.shared.u64 t, %1; cvt.u32.u64 %0, t; }" : "=r"(a) : "l"(p));
    return a;
}
#define SW128(off) ((off) ^ (((off) >> 3) & 0x70))

__device__ __forceinline__ void cp16(uint32_t dst, const void* src) {
    asm volatile("cp.async.cg.shared.global [%0], [%1], 16;" :: "r"(dst), "l"(src));
}

#define LDSM_X4(r, a) \
    asm volatile("ldmatrix.sync.aligned.m8n8.x4.shared.b16 {%0,%1,%2,%3}, [%4];" \
        : "=r"((r)[0]), "=r"((r)[1]), "=r"((r)[2]), "=r"((r)[3]) : "r"(a))

#define MMA16816(d, a, b0, b1) \
    asm volatile("mma.sync.aligned.m16n8k16.row.col.f32.bf16.bf16.f32 " \
        "{%0,%1,%2,%3}, {%4,%5,%6,%7}, {%8,%9}, {%0,%1,%2,%3};" \
        : "+f"((d)[0]), "+f"((d)[1]), "+f"((d)[2]), "+f"((d)[3]) \
        : "r"((a)[0]), "r"((a)[1]), "r"((a)[2]), "r"((a)[3]), "r"(b0), "r"(b1))

// ---------------- Kernel 1: guide FC  g = guide @ Wg^T + bg ----------------
__global__ void guide_gemm(const float* __restrict__ guide,
                           const float* __restrict__ Wg,
                           const float* __restrict__ bg) {
    __shared__ float As[32][33];
    __shared__ float Bs[32][33];
    int tid  = threadIdx.x;
    int row0 = blockIdx.x * 32;
    int col0 = blockIdx.y * 32;
    int tx = tid & 31, ty = tid >> 5;
    float acc[4] = {0.f, 0.f, 0.f, 0.f};
    for (int kc = 0; kc < CG; kc += 32) {
        int r = tid >> 3, kq = (tid & 7) * 4;
        float4 a4 = *reinterpret_cast<const float4*>(&guide[(size_t)(row0 + r) * CG + kc + kq]);
        As[r][kq] = a4.x; As[r][kq + 1] = a4.y; As[r][kq + 2] = a4.z; As[r][kq + 3] = a4.w;
        float4 b4 = *reinterpret_cast<const float4*>(&Wg[(size_t)(col0 + r) * CG + kc + kq]);
        Bs[r][kq] = b4.x; Bs[r][kq + 1] = b4.y; Bs[r][kq + 2] = b4.z; Bs[r][kq + 3] = b4.w;
        __syncthreads();
        #pragma unroll
        for (int k = 0; k < 32; k++) {
            float bv = Bs[tx][k];
            #pragma unroll
            for (int rr = 0; rr < 4; rr++)
                acc[rr] += As[ty + 8 * rr][k] * bv;
        }
        __syncthreads();
    }
    float bias = bg[col0 + tx];
    #pragma unroll
    for (int rr = 0; rr < 4; rr++)
        g_buf[(size_t)(row0 + ty + 8 * rr) * EE + col0 + tx] = acc[rr] + bias;
}

// -------- Kernel 2: embed 1x1 conv + BN, output layout [b][hw][e] ----------
__global__ void embed_gemm(const float* __restrict__ x,
                           const float* __restrict__ We,
                           const float* __restrict__ gamma_e,
                           const float* __restrict__ beta_e) {
    __shared__ __align__(16) float xs[16 * 64];
    __shared__ __align__(16) float ws[16 * 68];
    int tid = threadIdx.x;
    int hw0 = blockIdx.x * 64;
    int e0  = blockIdx.y * 64;
    int b   = blockIdx.z;
    int tx = tid & 15, ty = tid >> 4;
    float acc[4][4] = {};
    const float* xb = x + (size_t)b * CIN * HW;
    for (int kc = 0; kc < CIN; kc += 16) {
        {
            int kk = tid >> 4, h0 = (tid & 15) * 4;
            float4 v = *reinterpret_cast<const float4*>(&xb[(size_t)(kc + kk) * HW + hw0 + h0]);
            *reinterpret_cast<float4*>(&xs[kk * 64 + h0]) = v;
            int el = tid >> 2, kq = (tid & 3) * 4;
            float4 wv = *reinterpret_cast<const float4*>(&We[(size_t)(e0 + el) * CIN + kc + kq]);
            ws[(kq + 0) * 68 + el] = wv.x;
            ws[(kq + 1) * 68 + el] = wv.y;
            ws[(kq + 2) * 68 + el] = wv.z;
            ws[(kq + 3) * 68 + el] = wv.w;
        }
        __syncthreads();
        #pragma unroll
        for (int kk = 0; kk < 16; kk++) {
            float4 av = *reinterpret_cast<const float4*>(&xs[kk * 64 + ty * 4]);
            float4 bv = *reinterpret_cast<const float4*>(&ws[kk * 68 + tx * 4]);
            float a[4] = {av.x, av.y, av.z, av.w};
            float bw[4] = {bv.x, bv.y, bv.z, bv.w};
            #pragma unroll
            for (int i = 0; i < 4; i++)
                #pragma unroll
                for (int j = 0; j < 4; j++)
                    acc[i][j] += a[i] * bw[j];
        }
        __syncthreads();
    }
    int e = e0 + tx * 4;
    float sc[4], bt[4];
    #pragma unroll
    for (int j = 0; j < 4; j++) {
        sc[j] = gamma_e[e + j] * rsqrtf(1.0f + BN_EPS);
        bt[j] = beta_e[e + j];
    }
    #pragma unroll
    for (int i = 0; i < 4; i++) {
        int hw = hw0 + ty * 4 + i;
        float4 o;
        o.x = acc[i][0] * sc[0] + bt[0];
        o.y = acc[i][1] * sc[1] + bt[1];
        o.z = acc[i][2] * sc[2] + bt[2];
        o.w = acc[i][3] * sc[3] + bt[3];
        *reinterpret_cast<float4*>(&e_buf[((size_t)b * HW + hw) * EE + e]) = o;
    }
}

// -------- Kernel 3: attn = sigmoid(max_n <e, g>/sqrt(C) + head_bias) -------
__global__ void attn_kernel(const float* __restrict__ head_bias) {
    __shared__ __align__(16) float gs[NTOK * HC];
    int tid = threadIdx.x;
    int hw0 = blockIdx.x * 128;
    int m   = blockIdx.y;
    int b   = blockIdx.z;
    for (int idx = tid; idx < NTOK * HC; idx += 128) {
        int n = idx >> 5, c = idx & 31;
        gs[idx] = g_buf[((size_t)(b * NTOK + n)) * EE + m * HC + c];
    }
    __syncthreads();
    int hw = hw0 + tid;
    if (hw >= HW) return;
    float4 ev[8];
    const float* ep = &e_buf[((size_t)b * HW + hw) * EE + m * HC];
    #pragma unroll
    for (int j = 0; j < 8; j++) ev[j] = reinterpret_cast<const float4*>(ep)[j];
    float maxv = -3.4e38f;
    for (int n = 0; n < NTOK; n++) {
        const float4* gp = reinterpret_cast<const float4*>(&gs[n * HC]);
        float acc = 0.f;
        #pragma unroll
        for (int j = 0; j < 8; j++) {
            float4 g4 = gp[j];
            acc += ev[j].x * g4.x + ev[j].y * g4.y + ev[j].z * g4.z + ev[j].w * g4.w;
        }
        maxv = fmaxf(maxv, acc);
    }
    float a = maxv * 0.17677669529663687f + head_bias[m];
    float s = 1.0f / (1.0f + expf(-a));
    attn_buf[(size_t)(b * NH + m) * HW + hw] = s;
}

// ---------------- prep: weights -> wk_hi/lo[k][co][ci] bf16 ----------------
__global__ void wprep(const float* __restrict__ Wp) {
    int co = blockIdx.x;
    for (int ci = threadIdx.x; ci < CIN; ci += 256) {
        const float* src = Wp + ((size_t)co * CIN + ci) * 9;
        #pragma unroll
        for (int k = 0; k < 9; k++) {
            float v = src[k];
            __nv_bfloat16 hi = __float2bfloat16(v);
            __nv_bfloat16 lo = __float2bfloat16(v - __bfloat162float(hi));
            size_t off = ((size_t)k * COUT + co) * CIN + ci;
            wk_hi[off] = hi;
            wk_lo[off] = lo;
        }
    }
}

// ------------- prep: x -> xsh_hi/lo[kw][b][p][ci] shifted bf16 -------------
__global__ void xprep(const float* __restrict__ x) {
    __shared__ float s[64][41];
    int pr = blockIdx.x;        // padded row 0..47 (x row pr-1)
    int cc = blockIdx.y * 64;   // ci chunk
    int b  = blockIdx.z;
    int hr = pr - 1;
    bool rowvalid = (hr >= 0 && hr < HH);
    for (int idx = threadIdx.x; idx < 64 * 40; idx += 256) {
        int ci = idx / 40, w = idx % 40;
        s[ci][w] = rowvalid ? x[((size_t)(b * CIN + cc + ci)) * HW + hr * WW + w] : 0.f;
    }
    __syncthreads();
    for (int idx = threadIdx.x; idx < 3 * 40 * 64; idx += 256) {
        int kw = idx / 2560, rem = idx % 2560, w = rem / 64, ci = rem % 64;
        int ws = w + kw - 1;
        float v = (rowvalid && ws >= 0 && ws < WW) ? s[ci][ws] : 0.f;
        __nv_bfloat16 hi = __float2bfloat16(v);
        __nv_bfloat16 lo = __float2bfloat16(v - __bfloat162float(hi));
        size_t off = (((size_t)(kw * BB + b)) * PPAD + pr * 40 + w) * CIN + cc + ci;
        xsh_hi[off] = hi;
        xsh_lo[off] = lo;
    }
}

// ------- conv 3x3: 9 shifted bf16 hi/lo GEMMs via mma.sync (HMMA) ----------
// CTA 128 co x 128 q; 72 K-steps of 64 ci; 3-stage cp.async pipeline.
#define CSTAGE  65536       // Ahi 16K | Alo 16K | Bhi 16K | Blo 16K
#define A_LO    16384
#define B_HI    32768
#define B_LO    49152
#define CSMEM   196608      // 3 stages
#define CNSTEP  72

__device__ __forceinline__ void conv_load_step(uint32_t sb, int s, int cobase,
                                               int q0, int b, int tid) {
    int k = s >> 3, cc = s & 7;
    int kh = k / 3, kw = k - kh * 3;
    uint32_t st = sb + (uint32_t)(s % 3) * CSTAGE;
    const char* srcs[4];
    srcs[0] = (const char*)(wk_hi + ((size_t)k * COUT + cobase) * CIN + cc * 64);
    srcs[1] = (const char*)(wk_lo + ((size_t)k * COUT + cobase) * CIN + cc * 64);
    size_t xoff = (((size_t)(kw * BB + b)) * PPAD + q0 + kh * 40) * CIN + cc * 64;
    srcs[2] = (const char*)(xsh_hi + xoff);
    srcs[3] = (const char*)(xsh_lo + xoff);
    #pragma unroll
    for (int i = 0; i < 16; i++) {
        int id = tid + i * 256;
        int t = id >> 10, rem = id & 1023, row = rem >> 3, ch = rem & 7;
        uint32_t so = SW128(row * 128 + ch * 16);
        cp16(st + t * 16384 + so, srcs[t] + (size_t)row * 1024 + ch * 16);
    }
    asm volatile("cp.async.commit_group;" ::: "memory");
}

__global__ void __launch_bounds__(256, 1)
conv_mma(const float* __restrict__ gamma_p,
         const float* __restrict__ beta_p,
         float* __restrict__ out) {
    extern __shared__ __align__(1024) char smem[];
    uint32_t sb = smem_u32(smem);
    int tid = threadIdx.x, wid = tid >> 5, lane = tid & 31;
    int q0     = blockIdx.x * 128;
    int cobase = blockIdx.y * 128;
    int b      = blockIdx.z;
    int wm = wid >> 2;      // 0..1  (64 co each == one head)
    int wn = wid & 3;       // 0..3  (32 q each)

    float acc[4][4][4];
    #pragma unroll
    for (int mt = 0; mt < 4; mt++)
        #pragma unroll
        for (int nt = 0; nt < 4; nt++)
            #pragma unroll
            for (int r = 0; r < 4; r++) acc[mt][nt][r] = 0.f;

    conv_load_step(sb, 0, cobase, q0, b, tid);
    conv_load_step(sb, 1, cobase, q0, b, tid);

    int lr    = lane & 15;
    int ahalf = ((lane >> 4) & 1) * 16;
    int brow  = ((lane >> 4) & 1) * 8 + (lane & 7);
    int bhalf = ((lane >> 3) & 1) * 16;

    for (int s = 0; s < CNSTEP; s++) {
        if (s < CNSTEP - 1) asm volatile("cp.async.wait_group 1;" ::: "memory");
        else                asm volatile("cp.async.wait_group 0;" ::: "memory");
        __syncthreads();
        if (s + 2 < CNSTEP) conv_load_step(sb, s + 2, cobase, q0, b, tid);

        uint32_t st = sb + (uint32_t)(s % 3) * CSTAGE;
        #pragma unroll
        for (int kk = 0; kk < 4; kk++) {
            uint32_t ahi[4][4], alo[4][4];
            #pragma unroll
            for (int mt = 0; mt < 4; mt++) {
                uint32_t off = SW128((uint32_t)(wm * 64 + mt * 16 + lr) * 128 + kk * 32 + ahalf);
                LDSM_X4(ahi[mt], st + off);
                LDSM_X4(alo[mt], st + A_LO + off);
            }
            uint32_t bhi[2][4], blo[2][4];
            #pragma unroll
            for (int bt = 0; bt < 2; bt++) {
                uint32_t off = SW128((uint32_t)(wn * 32 + bt * 16 + brow) * 128 + kk * 32 + bhalf);
                LDSM_X4(bhi[bt], st + B_HI + off);
                LDSM_X4(blo[bt], st + B_LO + off);
            }
            #pragma unroll
            for (int mt = 0; mt < 4; mt++)
                #pragma unroll
                for (int nt = 0; nt < 4; nt++) {
                    int bt = nt >> 1, pp = (nt & 1) * 2;
                    MMA16816(acc[mt][nt], ahi[mt], bhi[bt][pp], bhi[bt][pp + 1]);
                    MMA16816(acc[mt][nt], ahi[mt], blo[bt][pp], blo[bt][pp + 1]);
                    MMA16816(acc[mt][nt], alo[mt], bhi[bt][pp], bhi[bt][pp + 1]);
                }
        }
    }

    // ---------------- epilogue: BN + sigmoid gate, direct stores -----------
    int head = (cobase + wm * 64) >> 6;
    int qb = q0 + wn * 32;
    float av0[4], av1[4];
    bool qok[4];
    #pragma unroll
    for (int nt = 0; nt < 4; nt++) {
        int q = qb + nt * 8 + (lane & 3) * 2;
        qok[nt] = (q < HW);
        av0[nt] = qok[nt] ? attn_buf[(size_t)(b * NH + head) * HW + q] : 0.f;
        av1[nt] = qok[nt] ? attn_buf[(size_t)(b * NH + head) * HW + q + 1] : 0.f;
    }
    float inv = rsqrtf(1.0f + BN_EPS);
    #pragma unroll
    for (int mt = 0; mt < 4; mt++) {
        int r0 = cobase + wm * 64 + mt * 16 + (lane >> 2);
        float sc0 = gamma_p[r0] * inv,     bt0 = beta_p[r0];
        float sc8 = gamma_p[r0 + 8] * inv, bt8 = beta_p[r0 + 8];
        #pragma unroll
        for (int nt = 0; nt < 4; nt++) {
            if (!qok[nt]) continue;
            int q = qb + nt * 8 + (lane & 3) * 2;
            float2 v0, v1;
            v0.x = (acc[mt][nt][0] * sc0 + bt0) * av0[nt];
            v0.y = (acc[mt][nt][1] * sc0 + bt0) * av1[nt];
            v1.x = (acc[mt][nt][2] * sc8 + bt8) * av0[nt];
            v1.y = (acc[mt][nt][3] * sc8 + bt8) * av1[nt];
            *reinterpret_cast<float2*>(&out[((size_t)(b * COUT + r0)) * HW + q]) = v0;
            *reinterpret_cast<float2*>(&out[((size_t)(b * COUT + r0 + 8)) * HW + q]) = v1;
        }
    }
}

extern "C" void kernel_launch(void* const* d_in, const int* in_sizes, int n_in,
                              void* d_out, int out_size) {
    const float* x         = (const float*)d_in[0];
    const float* guide     = (const float*)d_in[1];
    const float* We        = (const float*)d_in[2];
    const float* gamma_e   = (const float*)d_in[3];
    const float* beta_e    = (const float*)d_in[4];
    const float* Wg        = (const float*)d_in[5];
    const float* bg        = (const float*)d_in[6];
    const float* head_bias = (const float*)d_in[7];
    const float* Wp        = (const float*)d_in[8];
    const float* gamma_p   = (const float*)d_in[9];
    const float* beta_p    = (const float*)d_in[10];
    float* out = (float*)d_out;

    guide_gemm<<<dim3(40, 8), 256>>>(guide, Wg, bg);
    embed_gemm<<<dim3(25, 4, 16), 256>>>(x, We, gamma_e, beta_e);
    attn_kernel<<<dim3(13, 8, 16), 128>>>(head_bias);
    wprep<<<512, 256>>>(Wp);
    xprep<<<dim3(48, 8, 16), 256>>>(x);
    cudaFuncSetAttribute(conv_mma, cudaFuncAttributeMaxDynamicSharedMemorySize, CSMEM);
    conv_mma<<<dim3(13, 4, 16), 256, CSMEM>>>(gamma_p, beta_p, out);
}

// round 5
// speedup vs baseline: 3.3691x; 1.1605x over previous
#include <cuda_runtime.h>
#include <cuda_bf16.h>
#include <cstdint>

#define BB   16
#define CIN  512
#define HH   40
#define WW   40
#define HW   1600
#define NTOK 80
#define CG   512
#define EE   256
#define COUT 512
#define NH   8
#define HC   32
#define BN_EPS 1e-3f
#define PPAD 1920   // 48 padded rows x 40 cols per image

// ------------------------------ scratch (device globals) -------------------
__device__ float g_buf[BB * NTOK * EE];
__device__ float e_buf[(size_t)BB * HW * EE];
__device__ float attn_buf[BB * NH * HW];
__device__ __align__(256) __nv_bfloat16 xsh_hi[(size_t)3 * BB * PPAD * CIN];
__device__ __align__(256) __nv_bfloat16 xsh_lo[(size_t)3 * BB * PPAD * CIN];
__device__ __align__(256) __nv_bfloat16 wk_hi[(size_t)9 * COUT * CIN];
__device__ __align__(256) __nv_bfloat16 wk_lo[(size_t)9 * COUT * CIN];
__device__ __align__(256) __nv_bfloat16 we_hi[EE * CIN];
__device__ __align__(256) __nv_bfloat16 we_lo[EE * CIN];

// ------------------------------ helpers ------------------------------------
__device__ __forceinline__ uint32_t smem_u32(const void* p) {
    uint32_t a;
    asm("{ .reg .u64 t; cvta.to.shared.u64 t, %1; cvt.u32.u64 %0, t; }" : "=r"(a) : "l"(p));
    return a;
}
#define SW128(off) ((off) ^ (((off) >> 3) & 0x70))

__device__ __forceinline__ void cp16(uint32_t dst, const void* src) {
    asm volatile("cp.async.cg.shared.global [%0], [%1], 16;" :: "r"(dst), "l"(src));
}

#define LDSM_X4(r, a) \
    asm volatile("ldmatrix.sync.aligned.m8n8.x4.shared.b16 {%0,%1,%2,%3}, [%4];" \
        : "=r"((r)[0]), "=r"((r)[1]), "=r"((r)[2]), "=r"((r)[3]) : "r"(a))

#define MMA16816(d, a, b0, b1) \
    asm volatile("mma.sync.aligned.m16n8k16.row.col.f32.bf16.bf16.f32 " \
        "{%0,%1,%2,%3}, {%4,%5,%6,%7}, {%8,%9}, {%0,%1,%2,%3};" \
        : "+f"((d)[0]), "+f"((d)[1]), "+f"((d)[2]), "+f"((d)[3]) \
        : "r"((a)[0]), "r"((a)[1]), "r"((a)[2]), "r"((a)[3]), "r"(b0), "r"(b1))

// ---------------- Kernel 1: guide FC  g = guide @ Wg^T + bg ----------------
__global__ void guide_gemm(const float* __restrict__ guide,
                           const float* __restrict__ Wg,
                           const float* __restrict__ bg) {
    __shared__ float As[32][33];
    __shared__ float Bs[32][33];
    int tid  = threadIdx.x;
    int row0 = blockIdx.x * 32;
    int col0 = blockIdx.y * 32;
    int tx = tid & 31, ty = tid >> 5;
    float acc[4] = {0.f, 0.f, 0.f, 0.f};
    for (int kc = 0; kc < CG; kc += 32) {
        int r = tid >> 3, kq = (tid & 7) * 4;
        float4 a4 = *reinterpret_cast<const float4*>(&guide[(size_t)(row0 + r) * CG + kc + kq]);
        As[r][kq] = a4.x; As[r][kq + 1] = a4.y; As[r][kq + 2] = a4.z; As[r][kq + 3] = a4.w;
        float4 b4 = *reinterpret_cast<const float4*>(&Wg[(size_t)(col0 + r) * CG + kc + kq]);
        Bs[r][kq] = b4.x; Bs[r][kq + 1] = b4.y; Bs[r][kq + 2] = b4.z; Bs[r][kq + 3] = b4.w;
        __syncthreads();
        #pragma unroll
        for (int k = 0; k < 32; k++) {
            float bv = Bs[tx][k];
            #pragma unroll
            for (int rr = 0; rr < 4; rr++)
                acc[rr] += As[ty + 8 * rr][k] * bv;
        }
        __syncthreads();
    }
    float bias = bg[col0 + tx];
    #pragma unroll
    for (int rr = 0; rr < 4; rr++)
        g_buf[(size_t)(row0 + ty + 8 * rr) * EE + col0 + tx] = acc[rr] + bias;
}

// -------- Kernel 3: attn = sigmoid(max_n <e, g>/sqrt(C) + head_bias) -------
__global__ void attn_kernel(const float* __restrict__ head_bias) {
    __shared__ __align__(16) float gs[NTOK * HC];
    int tid = threadIdx.x;
    int hw0 = blockIdx.x * 128;
    int m   = blockIdx.y;
    int b   = blockIdx.z;
    for (int idx = tid; idx < NTOK * HC; idx += 128) {
        int n = idx >> 5, c = idx & 31;
        gs[idx] = g_buf[((size_t)(b * NTOK + n)) * EE + m * HC + c];
    }
    __syncthreads();
    int hw = hw0 + tid;
    if (hw >= HW) return;
    float4 ev[8];
    const float* ep = &e_buf[((size_t)b * HW + hw) * EE + m * HC];
    #pragma unroll
    for (int j = 0; j < 8; j++) ev[j] = reinterpret_cast<const float4*>(ep)[j];
    float maxv = -3.4e38f;
    for (int n = 0; n < NTOK; n++) {
        const float4* gp = reinterpret_cast<const float4*>(&gs[n * HC]);
        float acc = 0.f;
        #pragma unroll
        for (int j = 0; j < 8; j++) {
            float4 g4 = gp[j];
            acc += ev[j].x * g4.x + ev[j].y * g4.y + ev[j].z * g4.z + ev[j].w * g4.w;
        }
        maxv = fmaxf(maxv, acc);
    }
    float a = maxv * 0.17677669529663687f + head_bias[m];
    float s = 1.0f / (1.0f + expf(-a));
    attn_buf[(size_t)(b * NH + m) * HW + hw] = s;
}

// ---------------- prep: weights -> wk_hi/lo[k][co][ci] bf16 ----------------
__global__ void wprep(const float* __restrict__ Wp) {
    int co = blockIdx.x;
    for (int ci = threadIdx.x; ci < CIN; ci += 256) {
        const float* src = Wp + ((size_t)co * CIN + ci) * 9;
        #pragma unroll
        for (int k = 0; k < 9; k++) {
            float v = src[k];
            __nv_bfloat16 hi = __float2bfloat16(v);
            __nv_bfloat16 lo = __float2bfloat16(v - __bfloat162float(hi));
            size_t off = ((size_t)k * COUT + co) * CIN + ci;
            wk_hi[off] = hi;
            wk_lo[off] = lo;
        }
    }
}

// ---------------- prep: We -> we_hi/lo[e][ci] bf16 --------------------------
__global__ void weprep(const float* __restrict__ We) {
    int e = blockIdx.x;
    for (int ci = threadIdx.x; ci < CIN; ci += 256) {
        float v = We[(size_t)e * CIN + ci];
        __nv_bfloat16 hi = __float2bfloat16(v);
        __nv_bfloat16 lo = __float2bfloat16(v - __bfloat162float(hi));
        we_hi[(size_t)e * CIN + ci] = hi;
        we_lo[(size_t)e * CIN + ci] = lo;
    }
}

// ------------- prep: x -> xsh_hi/lo[kw][b][p][ci] shifted bf16 -------------
__global__ void xprep(const float* __restrict__ x) {
    __shared__ float s[64][41];
    int pr = blockIdx.x;        // padded row 0..47 (x row pr-1)
    int cc = blockIdx.y * 64;   // ci chunk
    int b  = blockIdx.z;
    int hr = pr - 1;
    bool rowvalid = (hr >= 0 && hr < HH);
    for (int idx = threadIdx.x; idx < 64 * 40; idx += 256) {
        int ci = idx / 40, w = idx % 40;
        s[ci][w] = rowvalid ? x[((size_t)(b * CIN + cc + ci)) * HW + hr * WW + w] : 0.f;
    }
    __syncthreads();
    for (int idx = threadIdx.x; idx < 3 * 40 * 64; idx += 256) {
        int kw = idx / 2560, rem = idx % 2560, w = rem / 64, ci = rem % 64;
        int ws = w + kw - 1;
        float v = (rowvalid && ws >= 0 && ws < WW) ? s[ci][ws] : 0.f;
        __nv_bfloat16 hi = __float2bfloat16(v);
        __nv_bfloat16 lo = __float2bfloat16(v - __bfloat162float(hi));
        size_t off = (((size_t)(kw * BB + b)) * PPAD + pr * 40 + w) * CIN + cc + ci;
        xsh_hi[off] = hi;
        xsh_lo[off] = lo;
    }
}

// ---------------- shared mma machinery: 256(M) x 128(N) CTA, 512 thr -------
#define CSTG   98304       // Ahi 32K | Alo 32K | Bhi 16K | Blo 16K
#define A_LO   32768
#define B_HI   65536
#define B_LO   81920
#define SMEMB  196608      // 2 stages

__device__ __forceinline__ void ld_step(uint32_t st, const char* wh, const char* wl,
                                        const char* xh, const char* xl, int tid) {
    #pragma unroll
    for (int i = 0; i < 8; i++) {        // A: 4096 cp16
        int id = tid + i * 512;
        int t = id >> 11, rem = id & 2047, row = rem >> 3, ch = rem & 7;
        uint32_t so = SW128(row * 128 + ch * 16);
        cp16(st + t * 32768 + so, (t ? wl : wh) + (size_t)row * 1024 + ch * 16);
    }
    #pragma unroll
    for (int i = 0; i < 4; i++) {        // B: 2048 cp16
        int id = tid + i * 512;
        int t = id >> 10, rem = id & 1023, row = rem >> 3, ch = rem & 7;
        uint32_t so = SW128(row * 128 + ch * 16);
        cp16(st + B_HI + t * 16384 + so, (t ? xl : xh) + (size_t)row * 1024 + ch * 16);
    }
    asm volatile("cp.async.commit_group;" ::: "memory");
}

struct Frag { float acc[4][4][4]; };

__device__ __forceinline__ void mma_step(uint32_t st, int wm, int wn, int lane,
                                         Frag& f) {
    int lr    = lane & 15;
    int ahalf = ((lane >> 4) & 1) * 16;
    int brow  = ((lane >> 4) & 1) * 8 + (lane & 7);
    int bhalf = ((lane >> 3) & 1) * 16;
    #pragma unroll
    for (int kk = 0; kk < 4; kk++) {
        uint32_t bhi[2][4], blo[2][4];
        #pragma unroll
        for (int bt = 0; bt < 2; bt++) {
            uint32_t off = SW128((uint32_t)(wn * 32 + bt * 16 + brow) * 128 + kk * 32 + bhalf);
            LDSM_X4(bhi[bt], st + B_HI + off);
            LDSM_X4(blo[bt], st + B_LO + off);
        }
        #pragma unroll
        for (int mt = 0; mt < 4; mt++) {
            uint32_t ahi[4], alo[4];
            uint32_t off = SW128((uint32_t)(wm * 64 + mt * 16 + lr) * 128 + kk * 32 + ahalf);
            LDSM_X4(ahi, st + off);
            LDSM_X4(alo, st + A_LO + off);
            #pragma unroll
            for (int nt = 0; nt < 4; nt++) {
                int bt = nt >> 1, pp = (nt & 1) * 2;
                MMA16816(f.acc[mt][nt], ahi, bhi[bt][pp], bhi[bt][pp + 1]);
                MMA16816(f.acc[mt][nt], ahi, blo[bt][pp], blo[bt][pp + 1]);
                MMA16816(f.acc[mt][nt], alo, bhi[bt][pp], bhi[bt][pp + 1]);
            }
        }
    }
}

// ------- conv 3x3: 9 shifted bf16 hi/lo GEMMs via mma.sync ------------------
#define CNSTEP 72

__device__ __forceinline__ void conv_load(uint32_t sb, int s, int cobase,
                                          int q0, int b, int tid) {
    int k = s >> 3, cc = s & 7;
    int kh = k / 3, kw = k - kh * 3;
    uint32_t st = sb + (uint32_t)(s & 1) * CSTG;
    const char* wh = (const char*)(wk_hi + ((size_t)k * COUT + cobase) * CIN + cc * 64);
    const char* wl = (const char*)(wk_lo + ((size_t)k * COUT + cobase) * CIN + cc * 64);
    size_t xoff = (((size_t)(kw * BB + b)) * PPAD + q0 + kh * 40) * CIN + cc * 64;
    ld_step(st, wh, wl, (const char*)(xsh_hi + xoff), (const char*)(xsh_lo + xoff), tid);
}

__global__ void __launch_bounds__(512, 1)
conv_mma(const float* __restrict__ gamma_p,
         const float* __restrict__ beta_p,
         float* __restrict__ out) {
    extern __shared__ __align__(1024) char smem[];
    uint32_t sb = smem_u32(smem);
    int tid = threadIdx.x, wid = tid >> 5, lane = tid & 31;
    int q0     = blockIdx.x * 128;
    int cobase = blockIdx.y * 256;
    int b      = blockIdx.z;
    int wm = wid >> 2, wn = wid & 3;

    Frag f;
    #pragma unroll
    for (int mt = 0; mt < 4; mt++)
        #pragma unroll
        for (int nt = 0; nt < 4; nt++)
            #pragma unroll
            for (int r = 0; r < 4; r++) f.acc[mt][nt][r] = 0.f;

    conv_load(sb, 0, cobase, q0, b, tid);
    for (int s = 0; s < CNSTEP; s++) {
        asm volatile("cp.async.wait_group 0;" ::: "memory");
        __syncthreads();
        if (s + 1 < CNSTEP) conv_load(sb, s + 1, cobase, q0, b, tid);
        mma_step(sb + (uint32_t)(s & 1) * CSTG, wm, wn, lane, f);
    }

    // epilogue: BN + sigmoid gate, direct stores
    int head = (cobase + wm * 64) >> 6;
    int qb = q0 + wn * 32;
    float av0[4], av1[4];
    bool qok[4];
    #pragma unroll
    for (int nt = 0; nt < 4; nt++) {
        int q = qb + nt * 8 + (lane & 3) * 2;
        qok[nt] = (q < HW);
        av0[nt] = qok[nt] ? attn_buf[(size_t)(b * NH + head) * HW + q] : 0.f;
        av1[nt] = qok[nt] ? attn_buf[(size_t)(b * NH + head) * HW + q + 1] : 0.f;
    }
    float inv = rsqrtf(1.0f + BN_EPS);
    #pragma unroll
    for (int mt = 0; mt < 4; mt++) {
        int r0 = cobase + wm * 64 + mt * 16 + (lane >> 2);
        float sc0 = gamma_p[r0] * inv,     bt0 = beta_p[r0];
        float sc8 = gamma_p[r0 + 8] * inv, bt8 = beta_p[r0 + 8];
        #pragma unroll
        for (int nt = 0; nt < 4; nt++) {
            if (!qok[nt]) continue;
            int q = qb + nt * 8 + (lane & 3) * 2;
            float2 v0, v1;
            v0.x = (f.acc[mt][nt][0] * sc0 + bt0) * av0[nt];
            v0.y = (f.acc[mt][nt][1] * sc0 + bt0) * av1[nt];
            v1.x = (f.acc[mt][nt][2] * sc8 + bt8) * av0[nt];
            v1.y = (f.acc[mt][nt][3] * sc8 + bt8) * av1[nt];
            *reinterpret_cast<float2*>(&out[((size_t)(b * COUT + r0)) * HW + q]) = v0;
            *reinterpret_cast<float2*>(&out[((size_t)(b * COUT + r0 + 8)) * HW + q]) = v1;
        }
    }
}

// ------- embed 1x1 conv as bf16 hi/lo GEMM, M=256(E) x N=128(q), K=512 -----
#define ENSTEP 8

__device__ __forceinline__ void embed_load(uint32_t sb, int s, int q0, int b, int tid) {
    uint32_t st = sb + (uint32_t)(s & 1) * CSTG;
    const char* wh = (const char*)(we_hi + s * 64);
    const char* wl = (const char*)(we_lo + s * 64);
    size_t xoff = (((size_t)(BB + b)) * PPAD + q0 + 40) * CIN + s * 64;  // kw=1, kh=1
    ld_step(st, wh, wl, (const char*)(xsh_hi + xoff), (const char*)(xsh_lo + xoff), tid);
}

__global__ void __launch_bounds__(512, 1)
embed_mma(const float* __restrict__ gamma_e,
          const float* __restrict__ beta_e) {
    extern __shared__ __align__(1024) char smem[];
    uint32_t sb = smem_u32(smem);
    int tid = threadIdx.x, wid = tid >> 5, lane = tid & 31;
    int q0 = blockIdx.x * 128;
    int b  = blockIdx.z;
    int wm = wid >> 2, wn = wid & 3;

    Frag f;
    #pragma unroll
    for (int mt = 0; mt < 4; mt++)
        #pragma unroll
        for (int nt = 0; nt < 4; nt++)
            #pragma unroll
            for (int r = 0; r < 4; r++) f.acc[mt][nt][r] = 0.f;

    embed_load(sb, 0, q0, b, tid);
    for (int s = 0; s < ENSTEP; s++) {
        asm volatile("cp.async.wait_group 0;" ::: "memory");
        __syncthreads();
        if (s + 1 < ENSTEP) embed_load(sb, s + 1, q0, b, tid);
        mma_step(sb + (uint32_t)(s & 1) * CSTG, wm, wn, lane, f);
    }
    __syncthreads();

    // epilogue: BN, smem transpose, write e_buf[b][q][e]
    float* tile = reinterpret_cast<float*>(smem);
    int wbase = wid * 32 * 68;
    float inv = rsqrtf(1.0f + BN_EPS);
    #pragma unroll
    for (int mt = 0; mt < 4; mt++) {
        int er = mt * 16 + (lane >> 2);
        int eg = wm * 64 + er;
        float sc0 = gamma_e[eg] * inv,     bt0 = beta_e[eg];
        float sc8 = gamma_e[eg + 8] * inv, bt8 = beta_e[eg + 8];
        #pragma unroll
        for (int nt = 0; nt < 4; nt++) {
            int ql = nt * 8 + (lane & 3) * 2;
            tile[wbase + ql * 68 + er]           = f.acc[mt][nt][0] * sc0 + bt0;
            tile[wbase + (ql + 1) * 68 + er]     = f.acc[mt][nt][1] * sc0 + bt0;
            tile[wbase + ql * 68 + er + 8]       = f.acc[mt][nt][2] * sc8 + bt8;
            tile[wbase + (ql + 1) * 68 + er + 8] = f.acc[mt][nt][3] * sc8 + bt8;
        }
    }
    __syncwarp();
    #pragma unroll
    for (int i = 0; i < 16; i++) {
        int idx = i * 32 + lane;
        int row = idx >> 4, cg = idx & 15;
        int q = q0 + wn * 32 + row;
        if (q < HW) {
            float4 v = *reinterpret_cast<float4*>(&tile[wbase + row * 68 + cg * 4]);
            *reinterpret_cast<float4*>(&e_buf[((size_t)b * HW + q) * EE + wm * 64 + cg * 4]) = v;
        }
    }
}

extern "C" void kernel_launch(void* const* d_in, const int* in_sizes, int n_in,
                              void* d_out, int out_size) {
    const float* x         = (const float*)d_in[0];
    const float* guide     = (const float*)d_in[1];
    const float* We        = (const float*)d_in[2];
    const float* gamma_e   = (const float*)d_in[3];
    const float* beta_e    = (const float*)d_in[4];
    const float* Wg        = (const float*)d_in[5];
    const float* bg        = (const float*)d_in[6];
    const float* head_bias = (const float*)d_in[7];
    const float* Wp        = (const float*)d_in[8];
    const float* gamma_p   = (const float*)d_in[9];
    const float* beta_p    = (const float*)d_in[10];
    float* out = (float*)d_out;

    guide_gemm<<<dim3(40, 8), 256>>>(guide, Wg, bg);
    wprep<<<512, 256>>>(Wp);
    weprep<<<256, 256>>>(We);
    xprep<<<dim3(48, 8, 16), 256>>>(x);
    cudaFuncSetAttribute(embed_mma, cudaFuncAttributeMaxDynamicSharedMemorySize, SMEMB);
    embed_mma<<<dim3(13, 1, 16), 512, SMEMB>>>(gamma_e, beta_e);
    attn_kernel<<<dim3(13, 8, 16), 128>>>(head_bias);
    cudaFuncSetAttribute(conv_mma, cudaFuncAttributeMaxDynamicSharedMemorySize, SMEMB);
    conv_mma<<<dim3(13, 2, 16), 512, SMEMB>>>(gamma_p, beta_p, out);
}

// round 6
// speedup vs baseline: 4.5086x; 1.3382x over previous
#include <cuda_runtime.h>
#include <cuda_fp16.h>
#include <cstdint>

#define BB   16
#define CIN  512
#define HH   40
#define WW   40
#define HW   1600
#define NTOK 80
#define CG   512
#define EE   256
#define COUT 512
#define NH   8
#define HC   32
#define BN_EPS 1e-3f
#define PBUF 1920    // padded pixel slots per image (42-col space + guards)
#define XOFF 64      // guard offset: stored index = pi + XOFF, pi in [-43, 1835)

// ------------------------------ scratch (device globals) -------------------
__device__ float g_buf[BB * NTOK * EE];
__device__ float e_buf[(size_t)BB * HW * EE];
__device__ float attn_buf[BB * NH * HW];
__device__ __align__(256) __half xp_hi[(size_t)BB * PBUF * CIN];
__device__ __align__(256) __half xp_lo[(size_t)BB * PBUF * CIN];
__device__ __align__(256) __half wk_h[(size_t)9 * COUT * CIN];
__device__ __align__(256) __half we_h[EE * CIN];

// ------------------------------ helpers ------------------------------------
__device__ __forceinline__ uint32_t smem_u32(const void* p) {
    uint32_t a;
    asm("{ .reg .u64 t; cvta.to.shared.u64 t, %1; cvt.u32.u64 %0, t; }" : "=r"(a) : "l"(p));
    return a;
}
#define SW128(off) ((off) ^ (((off) >> 3) & 0x70))

__device__ __forceinline__ void cp16(uint32_t dst, const void* src) {
    asm volatile("cp.async.cg.shared.global [%0], [%1], 16;" :: "r"(dst), "l"(src));
}

#define LDSM_X4(r, a) \
    asm volatile("ldmatrix.sync.aligned.m8n8.x4.shared.b16 {%0,%1,%2,%3}, [%4];" \
        : "=r"((r)[0]), "=r"((r)[1]), "=r"((r)[2]), "=r"((r)[3]) : "r"(a))

#define MMA16816(d, a, b0, b1) \
    asm volatile("mma.sync.aligned.m16n8k16.row.col.f32.f16.f16.f32 " \
        "{%0,%1,%2,%3}, {%4,%5,%6,%7}, {%8,%9}, {%0,%1,%2,%3};" \
        : "+f"((d)[0]), "+f"((d)[1]), "+f"((d)[2]), "+f"((d)[3]) \
        : "r"((a)[0]), "r"((a)[1]), "r"((a)[2]), "r"((a)[3]), "r"(b0), "r"(b1))

// ---------------- Kernel 1: guide FC  g = guide @ Wg^T + bg ----------------
__global__ void guide_gemm(const float* __restrict__ guide,
                           const float* __restrict__ Wg,
                           const float* __restrict__ bg) {
    __shared__ float As[32][33];
    __shared__ float Bs[32][33];
    int tid  = threadIdx.x;
    int row0 = blockIdx.x * 32;
    int col0 = blockIdx.y * 32;
    int tx = tid & 31, ty = tid >> 5;
    float acc[4] = {0.f, 0.f, 0.f, 0.f};
    for (int kc = 0; kc < CG; kc += 32) {
        int r = tid >> 3, kq = (tid & 7) * 4;
        float4 a4 = *reinterpret_cast<const float4*>(&guide[(size_t)(row0 + r) * CG + kc + kq]);
        As[r][kq] = a4.x; As[r][kq + 1] = a4.y; As[r][kq + 2] = a4.z; As[r][kq + 3] = a4.w;
        float4 b4 = *reinterpret_cast<const float4*>(&Wg[(size_t)(col0 + r) * CG + kc + kq]);
        Bs[r][kq] = b4.x; Bs[r][kq + 1] = b4.y; Bs[r][kq + 2] = b4.z; Bs[r][kq + 3] = b4.w;
        __syncthreads();
        #pragma unroll
        for (int k = 0; k < 32; k++) {
            float bv = Bs[tx][k];
            #pragma unroll
            for (int rr = 0; rr < 4; rr++)
                acc[rr] += As[ty + 8 * rr][k] * bv;
        }
        __syncthreads();
    }
    float bias = bg[col0 + tx];
    #pragma unroll
    for (int rr = 0; rr < 4; rr++)
        g_buf[(size_t)(row0 + ty + 8 * rr) * EE + col0 + tx] = acc[rr] + bias;
}

// -------- attn = sigmoid(max_n <e, g>/sqrt(C) + head_bias) ------------------
__global__ void attn_kernel(const float* __restrict__ head_bias) {
    __shared__ __align__(16) float gs[NTOK * HC];
    int tid = threadIdx.x;
    int hw0 = blockIdx.x * 128;
    int m   = blockIdx.y;
    int b   = blockIdx.z;
    for (int idx = tid; idx < NTOK * HC; idx += 128) {
        int n = idx >> 5, c = idx & 31;
        gs[idx] = g_buf[((size_t)(b * NTOK + n)) * EE + m * HC + c];
    }
    __syncthreads();
    int hw = hw0 + tid;
    if (hw >= HW) return;
    float4 ev[8];
    const float* ep = &e_buf[((size_t)b * HW + hw) * EE + m * HC];
    #pragma unroll
    for (int j = 0; j < 8; j++) ev[j] = reinterpret_cast<const float4*>(ep)[j];
    float maxv = -3.4e38f;
    for (int n = 0; n < NTOK; n++) {
        const float4* gp = reinterpret_cast<const float4*>(&gs[n * HC]);
        float acc = 0.f;
        #pragma unroll
        for (int j = 0; j < 8; j++) {
            float4 g4 = gp[j];
            acc += ev[j].x * g4.x + ev[j].y * g4.y + ev[j].z * g4.z + ev[j].w * g4.w;
        }
        maxv = fmaxf(maxv, acc);
    }
    float a = maxv * 0.17677669529663687f + head_bias[m];
    float s = 1.0f / (1.0f + expf(-a));
    attn_buf[(size_t)(b * NH + m) * HW + hw] = s;
}

// ---------------- preps -----------------------------------------------------
__global__ void wprep(const float* __restrict__ Wp) {
    int co = blockIdx.x;
    for (int ci = threadIdx.x; ci < CIN; ci += 256) {
        const float* src = Wp + ((size_t)co * CIN + ci) * 9;
        #pragma unroll
        for (int k = 0; k < 9; k++)
            wk_h[((size_t)k * COUT + co) * CIN + ci] = __float2half(src[k]);
    }
}

__global__ void weprep(const float* __restrict__ We) {
    int e = blockIdx.x;
    for (int ci = threadIdx.x; ci < CIN; ci += 256)
        we_h[(size_t)e * CIN + ci] = __float2half(We[(size_t)e * CIN + ci]);
}

__global__ void zinit() {
    size_t i = (size_t)blockIdx.x * 256 + threadIdx.x;   // uint4 index
    uint4 z = {0, 0, 0, 0};
    reinterpret_cast<uint4*>(xp_hi)[i] = z;
    reinterpret_cast<uint4*>(xp_lo)[i] = z;
}

// x row r -> padded fp16 hi/lo at pi = (r+1)*42 + (c+1)
__global__ void xprep(const float* __restrict__ x) {
    __shared__ float s[64][41];
    int r  = blockIdx.x;
    int cc = blockIdx.y * 64;
    int b  = blockIdx.z;
    for (int idx = threadIdx.x; idx < 64 * 40; idx += 256) {
        int ci = idx / 40, c = idx % 40;
        s[ci][c] = x[((size_t)(b * CIN + cc + ci)) * HW + r * WW + c];
    }
    __syncthreads();
    for (int idx = threadIdx.x; idx < 40 * 64; idx += 256) {
        int c = idx >> 6, ci = idx & 63;
        float v = s[ci][c];
        __half hi = __float2half(v);
        __half lo = __float2half(v - __half2float(hi));
        size_t off = ((size_t)b * PBUF + XOFF + (r + 1) * 42 + (c + 1)) * CIN + cc + ci;
        xp_hi[off] = hi;
        xp_lo[off] = lo;
    }
}

// ---------------- shared mma machinery: 256(M) x 128(N) CTA, 512 thr -------
// stage: A 32K | Bhi 16K | Blo 16K = 64K, double buffered
#define CSTG   65536
#define B_HI   32768
#define B_LO   49152
#define CSMEM  131072
#define ESMEM  139264

__device__ __forceinline__ void ld_step(uint32_t st, const char* a_src,
                                        const char* bh, const char* bl, int tid) {
    #pragma unroll
    for (int i = 0; i < 4; i++) {        // A: 2048 cp16 (256 rows x 128B)
        int id = tid + i * 512;
        int row = id >> 3, ch = id & 7;
        cp16(st + SW128(row * 128 + ch * 16), a_src + (size_t)row * 1024 + ch * 16);
    }
    #pragma unroll
    for (int i = 0; i < 4; i++) {        // B: 2 x 1024 cp16 (128 rows x 128B)
        int id = tid + i * 512;
        int t = id >> 10, rem = id & 1023, row = rem >> 3, ch = rem & 7;
        uint32_t so = SW128(row * 128 + ch * 16);
        cp16(st + B_HI + t * 16384 + so, (t ? bl : bh) + (size_t)row * 1024 + ch * 16);
    }
    asm volatile("cp.async.commit_group;" ::: "memory");
}

struct Frag { float acc[4][4][4]; };

__device__ __forceinline__ void mma_step(uint32_t st, int wm, int wn, int lane,
                                         Frag& f) {
    int lr    = lane & 15;
    int ahalf = ((lane >> 4) & 1) * 16;
    int brow  = ((lane >> 4) & 1) * 8 + (lane & 7);
    int bhalf = ((lane >> 3) & 1) * 16;
    #pragma unroll
    for (int kk = 0; kk < 4; kk++) {
        uint32_t bh[2][4], bl[2][4];
        #pragma unroll
        for (int bt = 0; bt < 2; bt++) {
            uint32_t off = SW128((uint32_t)(wn * 32 + bt * 16 + brow) * 128 + kk * 32 + bhalf);
            LDSM_X4(bh[bt], st + B_HI + off);
            LDSM_X4(bl[bt], st + B_LO + off);
        }
        #pragma unroll
        for (int mt = 0; mt < 4; mt++) {
            uint32_t a[4];
            uint32_t off = SW128((uint32_t)(wm * 64 + mt * 16 + lr) * 128 + kk * 32 + ahalf);
            LDSM_X4(a, st + off);
            #pragma unroll
            for (int nt = 0; nt < 4; nt++) {
                int bt = nt >> 1, pp = (nt & 1) * 2;
                MMA16816(f.acc[mt][nt], a, bh[bt][pp], bh[bt][pp + 1]);
                MMA16816(f.acc[mt][nt], a, bl[bt][pp], bl[bt][pp + 1]);
            }
        }
    }
}

// ------- conv 3x3: 9 linear-offset taps in 42-col padded space --------------
#define CNSTEP 72

__device__ __forceinline__ void conv_load(uint32_t sb, int s, int cobase,
                                          int q0, int b, int tid) {
    int k = s >> 3, cc = s & 7;
    int kh = k / 3, kw = k - kh * 3;
    uint32_t st = sb + (uint32_t)(s & 1) * CSTG;
    const char* a_src = (const char*)(wk_h + ((size_t)k * COUT + cobase) * CIN + cc * 64);
    size_t xoff = ((size_t)b * PBUF + XOFF + q0 + (kh - 1) * 42 + (kw - 1)) * CIN + cc * 64;
    ld_step(st, a_src, (const char*)(xp_hi + xoff), (const char*)(xp_lo + xoff), tid);
}

__global__ void __launch_bounds__(512, 1)
conv_mma(const float* __restrict__ gamma_p,
         const float* __restrict__ beta_p,
         float* __restrict__ out) {
    extern __shared__ __align__(1024) char smem[];
    uint32_t sb = smem_u32(smem);
    int tid = threadIdx.x, wid = tid >> 5, lane = tid & 31;
    int q0     = blockIdx.x * 128;
    int cobase = blockIdx.y * 256;
    int b      = blockIdx.z;
    int wm = wid >> 2, wn = wid & 3;

    Frag f;
    #pragma unroll
    for (int mt = 0; mt < 4; mt++)
        #pragma unroll
        for (int nt = 0; nt < 4; nt++)
            #pragma unroll
            for (int r = 0; r < 4; r++) f.acc[mt][nt][r] = 0.f;

    conv_load(sb, 0, cobase, q0, b, tid);
    for (int s = 0; s < CNSTEP; s++) {
        asm volatile("cp.async.wait_group 0;" ::: "memory");
        __syncthreads();
        if (s + 1 < CNSTEP) conv_load(sb, s + 1, cobase, q0, b, tid);
        mma_step(sb + (uint32_t)(s & 1) * CSTG, wm, wn, lane, f);
    }

    // epilogue: BN + sigmoid gate; map padded index -> (h,w); guarded stores
    int head = (cobase >> 6) + wm;
    int qb = q0 + wn * 32;
    float inv = rsqrtf(1.0f + BN_EPS);
    #pragma unroll
    for (int mt = 0; mt < 4; mt++) {
        int r0 = cobase + wm * 64 + mt * 16 + (lane >> 2);
        float sc0 = gamma_p[r0] * inv,     bt0 = beta_p[r0];
        float sc8 = gamma_p[r0 + 8] * inv, bt8 = beta_p[r0 + 8];
        #pragma unroll
        for (int nt = 0; nt < 4; nt++) {
            int q = qb + nt * 8 + (lane & 3) * 2;
            #pragma unroll
            for (int e = 0; e < 2; e++) {
                int qq = q + e;
                int pr = qq / 42, pc = qq - pr * 42;
                if (pr >= 1 && pr <= 40 && pc >= 1 && pc <= 40) {
                    int hw = (pr - 1) * 40 + (pc - 1);
                    float av = attn_buf[(size_t)(b * NH + head) * HW + hw];
                    out[((size_t)(b * COUT + r0)) * HW + hw]     = (f.acc[mt][nt][e]     * sc0 + bt0) * av;
                    out[((size_t)(b * COUT + r0 + 8)) * HW + hw] = (f.acc[mt][nt][e + 2] * sc8 + bt8) * av;
                }
            }
        }
    }
}

// ------- embed 1x1 conv: center tap, M=256(E) x N=128(q), K=512 -------------
#define ENSTEP 8

__device__ __forceinline__ void embed_load(uint32_t sb, int s, int q0, int b, int tid) {
    uint32_t st = sb + (uint32_t)(s & 1) * CSTG;
    const char* a_src = (const char*)(we_h + s * 64);
    size_t xoff = ((size_t)b * PBUF + XOFF + q0) * CIN + s * 64;
    ld_step(st, a_src, (const char*)(xp_hi + xoff), (const char*)(xp_lo + xoff), tid);
}

__global__ void __launch_bounds__(512, 1)
embed_mma(const float* __restrict__ gamma_e,
          const float* __restrict__ beta_e) {
    extern __shared__ __align__(1024) char smem[];
    uint32_t sb = smem_u32(smem);
    int tid = threadIdx.x, wid = tid >> 5, lane = tid & 31;
    int q0 = blockIdx.x * 128;
    int b  = blockIdx.z;
    int wm = wid >> 2, wn = wid & 3;

    Frag f;
    #pragma unroll
    for (int mt = 0; mt < 4; mt++)
        #pragma unroll
        for (int nt = 0; nt < 4; nt++)
            #pragma unroll
            for (int r = 0; r < 4; r++) f.acc[mt][nt][r] = 0.f;

    embed_load(sb, 0, q0, b, tid);
    for (int s = 0; s < ENSTEP; s++) {
        asm volatile("cp.async.wait_group 0;" ::: "memory");
        __syncthreads();
        if (s + 1 < ENSTEP) embed_load(sb, s + 1, q0, b, tid);
        mma_step(sb + (uint32_t)(s & 1) * CSTG, wm, wn, lane, f);
    }
    __syncthreads();

    // epilogue: BN, smem transpose, guarded write to e_buf[b][hw][e]
    float* tile = reinterpret_cast<float*>(smem);
    int wbase = wid * 32 * 68;
    float inv = rsqrtf(1.0f + BN_EPS);
    #pragma unroll
    for (int mt = 0; mt < 4; mt++) {
        int er = mt * 16 + (lane >> 2);
        int eg = wm * 64 + er;
        float sc0 = gamma_e[eg] * inv,     bt0 = beta_e[eg];
        float sc8 = gamma_e[eg + 8] * inv, bt8 = beta_e[eg + 8];
        #pragma unroll
        for (int nt = 0; nt < 4; nt++) {
            int ql = nt * 8 + (lane & 3) * 2;
            tile[wbase + ql * 68 + er]           = f.acc[mt][nt][0] * sc0 + bt0;
            tile[wbase + (ql + 1) * 68 + er]     = f.acc[mt][nt][1] * sc0 + bt0;
            tile[wbase + ql * 68 + er + 8]       = f.acc[mt][nt][2] * sc8 + bt8;
            tile[wbase + (ql + 1) * 68 + er + 8] = f.acc[mt][nt][3] * sc8 + bt8;
        }
    }
    __syncwarp();
    #pragma unroll
    for (int i = 0; i < 16; i++) {
        int idx = i * 32 + lane;
        int row = idx >> 4, cg = idx & 15;
        int q = q0 + wn * 32 + row;
        int pr = q / 42, pc = q - pr * 42;
        if (pr >= 1 && pr <= 40 && pc >= 1 && pc <= 40) {
            int hw = (pr - 1) * 40 + (pc - 1);
            float4 v = *reinterpret_cast<float4*>(&tile[wbase + row * 68 + cg * 4]);
            *reinterpret_cast<float4*>(&e_buf[((size_t)b * HW + hw) * EE + wm * 64 + cg * 4]) = v;
        }
    }
}

extern "C" void kernel_launch(void* const* d_in, const int* in_sizes, int n_in,
                              void* d_out, int out_size) {
    const float* x         = (const float*)d_in[0];
    const float* guide     = (const float*)d_in[1];
    const float* We        = (const float*)d_in[2];
    const float* gamma_e   = (const float*)d_in[3];
    const float* beta_e    = (const float*)d_in[4];
    const float* Wg        = (const float*)d_in[5];
    const float* bg        = (const float*)d_in[6];
    const float* head_bias = (const float*)d_in[7];
    const float* Wp        = (const float*)d_in[8];
    const float* gamma_p   = (const float*)d_in[9];
    const float* beta_p    = (const float*)d_in[10];
    float* out = (float*)d_out;

    // 16*1920*512 halves / 8 per uint4 / 256 thr = 7680 blocks
    zinit<<<7680, 256>>>();
    guide_gemm<<<dim3(40, 8), 256>>>(guide, Wg, bg);
    wprep<<<512, 256>>>(Wp);
    weprep<<<256, 256>>>(We);
    xprep<<<dim3(40, 8, 16), 256>>>(x);
    cudaFuncSetAttribute(embed_mma, cudaFuncAttributeMaxDynamicSharedMemorySize, ESMEM);
    embed_mma<<<dim3(14, 1, 16), 512, ESMEM>>>(gamma_e, beta_e);
    attn_kernel<<<dim3(13, 8, 16), 128>>>(head_bias);
    cudaFuncSetAttribute(conv_mma, cudaFuncAttributeMaxDynamicSharedMemorySize, CSMEM);
    conv_mma<<<dim3(14, 2, 16), 512, CSMEM>>>(gamma_p, beta_p, out);
}

// round 7
// speedup vs baseline: 6.8063x; 1.5096x over previous
#include <cuda_runtime.h>
#include <cuda_fp16.h>
#include <cstdint>

#define BB   16
#define CIN  512
#define HH   40
#define WW   40
#define HW   1600
#define NTOK 80
#define CG   512
#define EE   256
#define COUT 512
#define NH   8
#define HC   32
#define BN_EPS 1e-3f
// 41-stride shared-pad pixel space: pi = r*41 + c, slot c=40 of each row = shared pad
#define PBUF 1792
#define XOFF 64

// ------------------------------ scratch (device globals) -------------------
__device__ float g_buf[BB * NTOK * EE];
__device__ float e_buf[(size_t)BB * HW * EE];
__device__ float attn_buf[BB * NH * HW];
__device__ __align__(256) __half xp_hi[(size_t)BB * PBUF * CIN];
__device__ __align__(256) __half xp_lo[(size_t)BB * PBUF * CIN];
__device__ __align__(256) __half wk_h[(size_t)9 * COUT * CIN];
__device__ __align__(256) __half we_h[EE * CIN];

// ------------------------------ helpers ------------------------------------
__device__ __forceinline__ uint32_t smem_u32(const void* p) {
    uint32_t a;
    asm("{ .reg .u64 t; cvta.to.shared.u64 t, %1; cvt.u32.u64 %0, t; }" : "=r"(a) : "l"(p));
    return a;
}
#define SW128(off) ((off) ^ (((off) >> 3) & 0x70))

__device__ __forceinline__ void cp16(uint32_t dst, const void* src) {
    asm volatile("cp.async.cg.shared.global [%0], [%1], 16;" :: "r"(dst), "l"(src));
}

#define LDSM_X4(r, a) \
    asm volatile("ldmatrix.sync.aligned.m8n8.x4.shared.b16 {%0,%1,%2,%3}, [%4];" \
        : "=r"((r)[0]), "=r"((r)[1]), "=r"((r)[2]), "=r"((r)[3]) : "r"(a))

#define MMA16816(d, a, b0, b1) \
    asm volatile("mma.sync.aligned.m16n8k16.row.col.f32.f16.f16.f32 " \
        "{%0,%1,%2,%3}, {%4,%5,%6,%7}, {%8,%9}, {%0,%1,%2,%3};" \
        : "+f"((d)[0]), "+f"((d)[1]), "+f"((d)[2]), "+f"((d)[3]) \
        : "r"((a)[0]), "r"((a)[1]), "r"((a)[2]), "r"((a)[3]), "r"(b0), "r"(b1))

// ---------------- Kernel 1: guide FC  g = guide @ Wg^T + bg ----------------
__global__ void guide_gemm(const float* __restrict__ guide,
                           const float* __restrict__ Wg,
                           const float* __restrict__ bg) {
    __shared__ float As[32][33];
    __shared__ float Bs[32][33];
    int tid  = threadIdx.x;
    int row0 = blockIdx.x * 32;
    int col0 = blockIdx.y * 32;
    int tx = tid & 31, ty = tid >> 5;
    float acc[4] = {0.f, 0.f, 0.f, 0.f};
    for (int kc = 0; kc < CG; kc += 32) {
        int r = tid >> 3, kq = (tid & 7) * 4;
        float4 a4 = *reinterpret_cast<const float4*>(&guide[(size_t)(row0 + r) * CG + kc + kq]);
        As[r][kq] = a4.x; As[r][kq + 1] = a4.y; As[r][kq + 2] = a4.z; As[r][kq + 3] = a4.w;
        float4 b4 = *reinterpret_cast<const float4*>(&Wg[(size_t)(col0 + r) * CG + kc + kq]);
        Bs[r][kq] = b4.x; Bs[r][kq + 1] = b4.y; Bs[r][kq + 2] = b4.z; Bs[r][kq + 3] = b4.w;
        __syncthreads();
        #pragma unroll
        for (int k = 0; k < 32; k++) {
            float bv = Bs[tx][k];
            #pragma unroll
            for (int rr = 0; rr < 4; rr++)
                acc[rr] += As[ty + 8 * rr][k] * bv;
        }
        __syncthreads();
    }
    float bias = bg[col0 + tx];
    #pragma unroll
    for (int rr = 0; rr < 4; rr++)
        g_buf[(size_t)(row0 + ty + 8 * rr) * EE + col0 + tx] = acc[rr] + bias;
}

// -------- attn = sigmoid(max_n <e, g>/sqrt(C) + head_bias) ------------------
__global__ void attn_kernel(const float* __restrict__ head_bias) {
    __shared__ __align__(16) float gs[NTOK * HC];
    int tid = threadIdx.x;
    int hw0 = blockIdx.x * 128;
    int m   = blockIdx.y;
    int b   = blockIdx.z;
    for (int idx = tid; idx < NTOK * HC; idx += 128) {
        int n = idx >> 5, c = idx & 31;
        gs[idx] = g_buf[((size_t)(b * NTOK + n)) * EE + m * HC + c];
    }
    __syncthreads();
    int hw = hw0 + tid;
    if (hw >= HW) return;
    float4 ev[8];
    const float* ep = &e_buf[((size_t)b * HW + hw) * EE + m * HC];
    #pragma unroll
    for (int j = 0; j < 8; j++) ev[j] = reinterpret_cast<const float4*>(ep)[j];
    float maxv = -3.4e38f;
    for (int n = 0; n < NTOK; n++) {
        const float4* gp = reinterpret_cast<const float4*>(&gs[n * HC]);
        float acc = 0.f;
        #pragma unroll
        for (int j = 0; j < 8; j++) {
            float4 g4 = gp[j];
            acc += ev[j].x * g4.x + ev[j].y * g4.y + ev[j].z * g4.z + ev[j].w * g4.w;
        }
        maxv = fmaxf(maxv, acc);
    }
    float a = maxv * 0.17677669529663687f + head_bias[m];
    float s = 1.0f / (1.0f + expf(-a));
    attn_buf[(size_t)(b * NH + m) * HW + hw] = s;
}

// ---------------- preps -----------------------------------------------------
__global__ void wprep(const float* __restrict__ Wp) {
    int co = blockIdx.x;
    for (int ci = threadIdx.x; ci < CIN; ci += 256) {
        const float* src = Wp + ((size_t)co * CIN + ci) * 9;
        #pragma unroll
        for (int k = 0; k < 9; k++)
            wk_h[((size_t)k * COUT + co) * CIN + ci] = __float2half(src[k]);
    }
}

__global__ void weprep(const float* __restrict__ We) {
    int e = blockIdx.x;
    for (int ci = threadIdx.x; ci < CIN; ci += 256)
        we_h[(size_t)e * CIN + ci] = __float2half(We[(size_t)e * CIN + ci]);
}

__global__ void zinit() {
    size_t i = (size_t)blockIdx.x * 256 + threadIdx.x;   // uint4 index
    uint4 z = {0, 0, 0, 0};
    reinterpret_cast<uint4*>(xp_hi)[i] = z;
    reinterpret_cast<uint4*>(xp_lo)[i] = z;
}

// x(r,c) -> padded fp16 hi/lo at pi = r*41 + c
__global__ void xprep(const float* __restrict__ x) {
    __shared__ float s[64][41];
    int r  = blockIdx.x;
    int cc = blockIdx.y * 64;
    int b  = blockIdx.z;
    for (int idx = threadIdx.x; idx < 64 * 40; idx += 256) {
        int ci = idx / 40, c = idx % 40;
        s[ci][c] = x[((size_t)(b * CIN + cc + ci)) * HW + r * WW + c];
    }
    __syncthreads();
    for (int idx = threadIdx.x; idx < 40 * 64; idx += 256) {
        int c = idx >> 6, ci = idx & 63;
        float v = s[ci][c];
        __half hi = __float2half(v);
        __half lo = __float2half(v - __half2float(hi));
        size_t off = ((size_t)b * PBUF + XOFF + r * 41 + c) * CIN + cc + ci;
        xp_hi[off] = hi;
        xp_lo[off] = lo;
    }
}

// ---------------- mma machinery: 256(M) x 128(N) CTA, 512 thr ---------------
struct Frag { float acc[4][4][4]; };

__device__ __forceinline__ void frag_zero(Frag& f) {
    #pragma unroll
    for (int mt = 0; mt < 4; mt++)
        #pragma unroll
        for (int nt = 0; nt < 4; nt++)
            #pragma unroll
            for (int r = 0; r < 4; r++) f.acc[mt][nt][r] = 0.f;
}

// ---- conv variant: 1 B product. stage = A 32K | Bhi 16K = 48K --------------
#define C_BHI  32768
#define CSTG   49152
#define CSMEM  98304
#define CNSTEP 72

__device__ __forceinline__ void ld_step1(uint32_t st, const char* a_src,
                                         const char* bh, int tid) {
    #pragma unroll
    for (int i = 0; i < 4; i++) {        // A: 2048 cp16 (256 rows x 128B)
        int id = tid + i * 512;
        int row = id >> 3, ch = id & 7;
        cp16(st + SW128(row * 128 + ch * 16), a_src + (size_t)row * 1024 + ch * 16);
    }
    #pragma unroll
    for (int i = 0; i < 2; i++) {        // B: 1024 cp16 (128 rows x 128B)
        int id = tid + i * 512;
        int row = id >> 3, ch = id & 7;
        cp16(st + C_BHI + SW128(row * 128 + ch * 16), bh + (size_t)row * 1024 + ch * 16);
    }
    asm volatile("cp.async.commit_group;" ::: "memory");
}

__device__ __forceinline__ void mma_step1(uint32_t st, int wm, int wn, int lane,
                                          Frag& f) {
    int lr    = lane & 15;
    int ahalf = ((lane >> 4) & 1) * 16;
    int brow  = ((lane >> 4) & 1) * 8 + (lane & 7);
    int bhalf = ((lane >> 3) & 1) * 16;
    #pragma unroll
    for (int kk = 0; kk < 4; kk++) {
        uint32_t bh[2][4];
        #pragma unroll
        for (int bt = 0; bt < 2; bt++) {
            uint32_t off = SW128((uint32_t)(wn * 32 + bt * 16 + brow) * 128 + kk * 32 + bhalf);
            LDSM_X4(bh[bt], st + C_BHI + off);
        }
        #pragma unroll
        for (int mt = 0; mt < 4; mt++) {
            uint32_t a[4];
            uint32_t off = SW128((uint32_t)(wm * 64 + mt * 16 + lr) * 128 + kk * 32 + ahalf);
            LDSM_X4(a, st + off);
            #pragma unroll
            for (int nt = 0; nt < 4; nt++) {
                int bt = nt >> 1, pp = (nt & 1) * 2;
                MMA16816(f.acc[mt][nt], a, bh[bt][pp], bh[bt][pp + 1]);
            }
        }
    }
}

__device__ __forceinline__ void conv_load(uint32_t sb, int s, int cobase,
                                          int q0, int b, int tid) {
    int k = s >> 3, cc = s & 7;
    int kh = k / 3, kw = k - kh * 3;
    uint32_t st = sb + (uint32_t)(s & 1) * CSTG;
    const char* a_src = (const char*)(wk_h + ((size_t)k * COUT + cobase) * CIN + cc * 64);
    size_t xoff = ((size_t)b * PBUF + XOFF + q0 + (kh - 1) * 41 + (kw - 1)) * CIN + cc * 64;
    ld_step1(st, a_src, (const char*)(xp_hi + xoff), tid);
}

__global__ void __launch_bounds__(512, 1)
conv_mma(const float* __restrict__ gamma_p,
         const float* __restrict__ beta_p,
         float* __restrict__ out) {
    extern __shared__ __align__(1024) char smem[];
    uint32_t sb = smem_u32(smem);
    int tid = threadIdx.x, wid = tid >> 5, lane = tid & 31;
    int q0     = blockIdx.x * 128;
    int cobase = blockIdx.y * 256;
    int b      = blockIdx.z;
    int wm = wid >> 2, wn = wid & 3;

    Frag f;
    frag_zero(f);

    conv_load(sb, 0, cobase, q0, b, tid);
    for (int s = 0; s < CNSTEP; s++) {
        asm volatile("cp.async.wait_group 0;" ::: "memory");
        __syncthreads();
        if (s + 1 < CNSTEP) conv_load(sb, s + 1, cobase, q0, b, tid);
        mma_step1(sb + (uint32_t)(s & 1) * CSTG, wm, wn, lane, f);
    }

    // epilogue: BN + sigmoid gate; pi -> (r,c); guarded stores
    int head = (cobase >> 6) + wm;
    int qb = q0 + wn * 32;
    float inv = rsqrtf(1.0f + BN_EPS);
    #pragma unroll
    for (int mt = 0; mt < 4; mt++) {
        int r0 = cobase + wm * 64 + mt * 16 + (lane >> 2);
        float sc0 = gamma_p[r0] * inv,     bt0 = beta_p[r0];
        float sc8 = gamma_p[r0 + 8] * inv, bt8 = beta_p[r0 + 8];
        #pragma unroll
        for (int nt = 0; nt < 4; nt++) {
            int q = qb + nt * 8 + (lane & 3) * 2;
            #pragma unroll
            for (int e = 0; e < 2; e++) {
                int qq = q + e;
                int pr = qq / 41, pc = qq - pr * 41;
                if (pc < 40 && pr < 40) {
                    int hw = pr * 40 + pc;
                    float av = attn_buf[(size_t)(b * NH + head) * HW + hw];
                    out[((size_t)(b * COUT + r0)) * HW + hw]     = (f.acc[mt][nt][e]     * sc0 + bt0) * av;
                    out[((size_t)(b * COUT + r0 + 8)) * HW + hw] = (f.acc[mt][nt][e + 2] * sc8 + bt8) * av;
                }
            }
        }
    }
}

// ---- embed variant: 2 B products. stage = A 32K | Bhi 16K | Blo 16K = 64K --
#define E_BHI  32768
#define E_BLO  49152
#define ESTG   65536
#define ESMEM  139264
#define ENSTEP 8

__device__ __forceinline__ void ld_step2(uint32_t st, const char* a_src,
                                         const char* bh, const char* bl, int tid) {
    #pragma unroll
    for (int i = 0; i < 4; i++) {
        int id = tid + i * 512;
        int row = id >> 3, ch = id & 7;
        cp16(st + SW128(row * 128 + ch * 16), a_src + (size_t)row * 1024 + ch * 16);
    }
    #pragma unroll
    for (int i = 0; i < 4; i++) {
        int id = tid + i * 512;
        int t = id >> 10, rem = id & 1023, row = rem >> 3, ch = rem & 7;
        uint32_t so = SW128(row * 128 + ch * 16);
        cp16(st + E_BHI + t * 16384 + so, (t ? bl : bh) + (size_t)row * 1024 + ch * 16);
    }
    asm volatile("cp.async.commit_group;" ::: "memory");
}

__device__ __forceinline__ void mma_step2(uint32_t st, int wm, int wn, int lane,
                                          Frag& f) {
    int lr    = lane & 15;
    int ahalf = ((lane >> 4) & 1) * 16;
    int brow  = ((lane >> 4) & 1) * 8 + (lane & 7);
    int bhalf = ((lane >> 3) & 1) * 16;
    #pragma unroll
    for (int kk = 0; kk < 4; kk++) {
        uint32_t bh[2][4], bl[2][4];
        #pragma unroll
        for (int bt = 0; bt < 2; bt++) {
            uint32_t off = SW128((uint32_t)(wn * 32 + bt * 16 + brow) * 128 + kk * 32 + bhalf);
            LDSM_X4(bh[bt], st + E_BHI + off);
            LDSM_X4(bl[bt], st + E_BLO + off);
        }
        #pragma unroll
        for (int mt = 0; mt < 4; mt++) {
            uint32_t a[4];
            uint32_t off = SW128((uint32_t)(wm * 64 + mt * 16 + lr) * 128 + kk * 32 + ahalf);
            LDSM_X4(a, st + off);
            #pragma unroll
            for (int nt = 0; nt < 4; nt++) {
                int bt = nt >> 1, pp = (nt & 1) * 2;
                MMA16816(f.acc[mt][nt], a, bh[bt][pp], bh[bt][pp + 1]);
                MMA16816(f.acc[mt][nt], a, bl[bt][pp], bl[bt][pp + 1]);
            }
        }
    }
}

__device__ __forceinline__ void embed_load(uint32_t sb, int s, int q0, int b, int tid) {
    uint32_t st = sb + (uint32_t)(s & 1) * ESTG;
    const char* a_src = (const char*)(we_h + s * 64);
    size_t xoff = ((size_t)b * PBUF + XOFF + q0) * CIN + s * 64;
    ld_step2(st, a_src, (const char*)(xp_hi + xoff), (const char*)(xp_lo + xoff), tid);
}

__global__ void __launch_bounds__(512, 1)
embed_mma(const float* __restrict__ gamma_e,
          const float* __restrict__ beta_e) {
    extern __shared__ __align__(1024) char smem[];
    uint32_t sb = smem_u32(smem);
    int tid = threadIdx.x, wid = tid >> 5, lane = tid & 31;
    int q0 = blockIdx.x * 128;
    int b  = blockIdx.z;
    int wm = wid >> 2, wn = wid & 3;

    Frag f;
    frag_zero(f);

    embed_load(sb, 0, q0, b, tid);
    for (int s = 0; s < ENSTEP; s++) {
        asm volatile("cp.async.wait_group 0;" ::: "memory");
        __syncthreads();
        if (s + 1 < ENSTEP) embed_load(sb, s + 1, q0, b, tid);
        mma_step2(sb + (uint32_t)(s & 1) * ESTG, wm, wn, lane, f);
    }
    __syncthreads();

    // epilogue: BN, smem transpose, guarded write to e_buf[b][hw][e]
    float* tile = reinterpret_cast<float*>(smem);
    int wbase = wid * 32 * 68;
    float inv = rsqrtf(1.0f + BN_EPS);
    #pragma unroll
    for (int mt = 0; mt < 4; mt++) {
        int er = mt * 16 + (lane >> 2);
        int eg = wm * 64 + er;
        float sc0 = gamma_e[eg] * inv,     bt0 = beta_e[eg];
        float sc8 = gamma_e[eg + 8] * inv, bt8 = beta_e[eg + 8];
        #pragma unroll
        for (int nt = 0; nt < 4; nt++) {
            int ql = nt * 8 + (lane & 3) * 2;
            tile[wbase + ql * 68 + er]           = f.acc[mt][nt][0] * sc0 + bt0;
            tile[wbase + (ql + 1) * 68 + er]     = f.acc[mt][nt][1] * sc0 + bt0;
            tile[wbase + ql * 68 + er + 8]       = f.acc[mt][nt][2] * sc8 + bt8;
            tile[wbase + (ql + 1) * 68 + er + 8] = f.acc[mt][nt][3] * sc8 + bt8;
        }
    }
    __syncwarp();
    #pragma unroll
    for (int i = 0; i < 16; i++) {
        int idx = i * 32 + lane;
        int row = idx >> 4, cg = idx & 15;
        int q = q0 + wn * 32 + row;
        int pr = q / 41, pc = q - pr * 41;
        if (pc < 40 && pr < 40) {
            int hw = pr * 40 + pc;
            float4 v = *reinterpret_cast<float4*>(&tile[wbase + row * 68 + cg * 4]);
            *reinterpret_cast<float4*>(&e_buf[((size_t)b * HW + hw) * EE + wm * 64 + cg * 4]) = v;
        }
    }
}

extern "C" void kernel_launch(void* const* d_in, const int* in_sizes, int n_in,
                              void* d_out, int out_size) {
    const float* x         = (const float*)d_in[0];
    const float* guide     = (const float*)d_in[1];
    const float* We        = (const float*)d_in[2];
    const float* gamma_e   = (const float*)d_in[3];
    const float* beta_e    = (const float*)d_in[4];
    const float* Wg        = (const float*)d_in[5];
    const float* bg        = (const float*)d_in[6];
    const float* head_bias = (const float*)d_in[7];
    const float* Wp        = (const float*)d_in[8];
    const float* gamma_p   = (const float*)d_in[9];
    const float* beta_p    = (const float*)d_in[10];
    float* out = (float*)d_out;

    // 16*1792*512 halves / 8 per uint4 / 256 thr = 7168 blocks
    zinit<<<7168, 256>>>();
    guide_gemm<<<dim3(40, 8), 256>>>(guide, Wg, bg);
    wprep<<<512, 256>>>(Wp);
    weprep<<<256, 256>>>(We);
    xprep<<<dim3(40, 8, 16), 256>>>(x);
    cudaFuncSetAttribute(embed_mma, cudaFuncAttributeMaxDynamicSharedMemorySize, ESMEM);
    embed_mma<<<dim3(13, 1, 16), 512, ESMEM>>>(gamma_e, beta_e);
    attn_kernel<<<dim3(13, 8, 16), 128>>>(head_bias);
    cudaFuncSetAttribute(conv_mma, cudaFuncAttributeMaxDynamicSharedMemorySize, CSMEM);
    conv_mma<<<dim3(13, 2, 16), 512, CSMEM>>>(gamma_p, beta_p, out);
}

// round 8
// speedup vs baseline: 7.1078x; 1.0443x over previous
#include <cuda_runtime.h>
#include <cuda_fp16.h>
#include <cstdint>

#define BB   16
#define CIN  512
#define HH   40
#define WW   40
#define HW   1600
#define NTOK 80
#define CG   512
#define EE   256
#define COUT 512
#define NH   8
#define HC   32
#define BN_EPS 1e-3f
// 41-stride shared-pad pixel space: pi = r*41 + c, slot c=40 of each row = shared pad
#define PBUF 1792
#define XOFF 64

// ------------------------------ scratch (device globals) -------------------
__device__ float g_buf[BB * NTOK * EE];
__device__ float attn_buf[BB * NH * HW];
__device__ __align__(256) __half xp_hi[(size_t)BB * PBUF * CIN];
__device__ __align__(256) __half wk_h[(size_t)9 * COUT * CIN];
__device__ __align__(256) __half we_h[EE * CIN];

// ------------------------------ helpers ------------------------------------
__device__ __forceinline__ uint32_t smem_u32(const void* p) {
    uint32_t a;
    asm("{ .reg .u64 t; cvta.to.shared.u64 t, %1; cvt.u32.u64 %0, t; }" : "=r"(a) : "l"(p));
    return a;
}
#define SW128(off) ((off) ^ (((off) >> 3) & 0x70))

__device__ __forceinline__ void cp16(uint32_t dst, const void* src) {
    asm volatile("cp.async.cg.shared.global [%0], [%1], 16;" :: "r"(dst), "l"(src));
}

#define LDSM_X4(r, a) \
    asm volatile("ldmatrix.sync.aligned.m8n8.x4.shared.b16 {%0,%1,%2,%3}, [%4];" \
        : "=r"((r)[0]), "=r"((r)[1]), "=r"((r)[2]), "=r"((r)[3]) : "r"(a))

#define MMA16816(d, a, b0, b1) \
    asm volatile("mma.sync.aligned.m16n8k16.row.col.f32.f16.f16.f32 " \
        "{%0,%1,%2,%3}, {%4,%5,%6,%7}, {%8,%9}, {%0,%1,%2,%3};" \
        : "+f"((d)[0]), "+f"((d)[1]), "+f"((d)[2]), "+f"((d)[3]) \
        : "r"((a)[0]), "r"((a)[1]), "r"((a)[2]), "r"((a)[3]), "r"(b0), "r"(b1))

// ---------------- Kernel 1: guide FC  g = guide @ Wg^T + bg ----------------
__global__ void guide_gemm(const float* __restrict__ guide,
                           const float* __restrict__ Wg,
                           const float* __restrict__ bg) {
    __shared__ float As[32][33];
    __shared__ float Bs[32][33];
    int tid  = threadIdx.x;
    int row0 = blockIdx.x * 32;
    int col0 = blockIdx.y * 32;
    int tx = tid & 31, ty = tid >> 5;
    float acc[4] = {0.f, 0.f, 0.f, 0.f};
    for (int kc = 0; kc < CG; kc += 32) {
        int r = tid >> 3, kq = (tid & 7) * 4;
        float4 a4 = *reinterpret_cast<const float4*>(&guide[(size_t)(row0 + r) * CG + kc + kq]);
        As[r][kq] = a4.x; As[r][kq + 1] = a4.y; As[r][kq + 2] = a4.z; As[r][kq + 3] = a4.w;
        float4 b4 = *reinterpret_cast<const float4*>(&Wg[(size_t)(col0 + r) * CG + kc + kq]);
        Bs[r][kq] = b4.x; Bs[r][kq + 1] = b4.y; Bs[r][kq + 2] = b4.z; Bs[r][kq + 3] = b4.w;
        __syncthreads();
        #pragma unroll
        for (int k = 0; k < 32; k++) {
            float bv = Bs[tx][k];
            #pragma unroll
            for (int rr = 0; rr < 4; rr++)
                acc[rr] += As[ty + 8 * rr][k] * bv;
        }
        __syncthreads();
    }
    float bias = bg[col0 + tx];
    #pragma unroll
    for (int rr = 0; rr < 4; rr++)
        g_buf[(size_t)(row0 + ty + 8 * rr) * EE + col0 + tx] = acc[rr] + bias;
}

// ---------------- preps -----------------------------------------------------
__global__ void wprep(const float* __restrict__ Wp) {
    int co = blockIdx.x;
    for (int ci = threadIdx.x; ci < CIN; ci += 256) {
        const float* src = Wp + ((size_t)co * CIN + ci) * 9;
        #pragma unroll
        for (int k = 0; k < 9; k++)
            wk_h[((size_t)k * COUT + co) * CIN + ci] = __float2half(src[k]);
    }
}

__global__ void weprep(const float* __restrict__ We) {
    int e = blockIdx.x;
    for (int ci = threadIdx.x; ci < CIN; ci += 256)
        we_h[(size_t)e * CIN + ci] = __float2half(We[(size_t)e * CIN + ci]);
}

__global__ void zinit() {
    size_t i = (size_t)blockIdx.x * 256 + threadIdx.x;   // uint4 index
    uint4 z = {0, 0, 0, 0};
    reinterpret_cast<uint4*>(xp_hi)[i] = z;
}

// x(r,c) -> padded fp16 at pi = r*41 + c
__global__ void xprep(const float* __restrict__ x) {
    __shared__ float s[64][41];
    int r  = blockIdx.x;
    int cc = blockIdx.y * 64;
    int b  = blockIdx.z;
    for (int idx = threadIdx.x; idx < 64 * 40; idx += 256) {
        int ci = idx / 40, c = idx % 40;
        s[ci][c] = x[((size_t)(b * CIN + cc + ci)) * HW + r * WW + c];
    }
    __syncthreads();
    for (int idx = threadIdx.x; idx < 40 * 64; idx += 256) {
        int c = idx >> 6, ci = idx & 63;
        size_t off = ((size_t)b * PBUF + XOFF + r * 41 + c) * CIN + cc + ci;
        xp_hi[off] = __float2half(s[ci][c]);
    }
}

// ---------------- mma machinery: 256(M) x 128(N), 8 warps, 64x64 warp tile --
#define S_BHI  32768
#define STG    49152       // A 32K | B 16K
#define CSMEM  98304       // conv: 2 stages

struct Frag { float acc[4][8][4]; };

__device__ __forceinline__ void frag_zero(Frag& f) {
    #pragma unroll
    for (int mt = 0; mt < 4; mt++)
        #pragma unroll
        for (int nt = 0; nt < 8; nt++)
            #pragma unroll
            for (int r = 0; r < 4; r++) f.acc[mt][nt][r] = 0.f;
}

__device__ __forceinline__ void ld_step(uint32_t st, const char* a_src,
                                        const char* bh, int tid) {
    #pragma unroll
    for (int i = 0; i < 8; i++) {        // A: 2048 cp16 (256 rows x 128B)
        int id = tid + i * 256;
        int row = id >> 3, ch = id & 7;
        cp16(st + SW128(row * 128 + ch * 16), a_src + (size_t)row * 1024 + ch * 16);
    }
    #pragma unroll
    for (int i = 0; i < 4; i++) {        // B: 1024 cp16 (128 rows x 128B)
        int id = tid + i * 256;
        int row = id >> 3, ch = id & 7;
        cp16(st + S_BHI + SW128(row * 128 + ch * 16), bh + (size_t)row * 1024 + ch * 16);
    }
    asm volatile("cp.async.commit_group;" ::: "memory");
}

__device__ __forceinline__ void mma_step(uint32_t st, int wm, int wn, int lane,
                                         Frag& f) {
    int lr    = lane & 15;
    int ahalf = ((lane >> 4) & 1) * 16;
    int brow  = ((lane >> 4) & 1) * 8 + (lane & 7);
    int bhalf = ((lane >> 3) & 1) * 16;
    #pragma unroll
    for (int kk = 0; kk < 4; kk++) {
        uint32_t bh[4][4];
        #pragma unroll
        for (int bt = 0; bt < 4; bt++) {
            uint32_t off = SW128((uint32_t)(wn * 64 + bt * 16 + brow) * 128 + kk * 32 + bhalf);
            LDSM_X4(bh[bt], st + S_BHI + off);
        }
        #pragma unroll
        for (int mt = 0; mt < 4; mt++) {
            uint32_t a[4];
            uint32_t off = SW128((uint32_t)(wm * 64 + mt * 16 + lr) * 128 + kk * 32 + ahalf);
            LDSM_X4(a, st + off);
            #pragma unroll
            for (int nt = 0; nt < 8; nt++) {
                int bt = nt >> 1, pp = (nt & 1) * 2;
                MMA16816(f.acc[mt][nt], a, bh[bt][pp], bh[bt][pp + 1]);
            }
        }
    }
}

// ------- conv 3x3: 9 linear-offset taps in 41-col padded space --------------
#define CNSTEP 72

__device__ __forceinline__ void conv_load(uint32_t sb, int s, int cobase,
                                          int q0, int b, int tid) {
    int k = s >> 3, cc = s & 7;
    int kh = k / 3, kw = k - kh * 3;
    uint32_t st = sb + (uint32_t)(s & 1) * STG;
    const char* a_src = (const char*)(wk_h + ((size_t)k * COUT + cobase) * CIN + cc * 64);
    size_t xoff = ((size_t)b * PBUF + XOFF + q0 + (kh - 1) * 41 + (kw - 1)) * CIN + cc * 64;
    ld_step(st, a_src, (const char*)(xp_hi + xoff), tid);
}

__global__ void __launch_bounds__(256, 1)
conv_mma(const float* __restrict__ gamma_p,
         const float* __restrict__ beta_p,
         float* __restrict__ out) {
    extern __shared__ __align__(1024) char smem[];
    uint32_t sb = smem_u32(smem);
    int tid = threadIdx.x, wid = tid >> 5, lane = tid & 31;
    int q0     = blockIdx.x * 128;
    int cobase = blockIdx.y * 256;
    int b      = blockIdx.z;
    int wm = wid >> 1, wn = wid & 1;

    Frag f;
    frag_zero(f);

    conv_load(sb, 0, cobase, q0, b, tid);
    for (int s = 0; s < CNSTEP; s++) {
        asm volatile("cp.async.wait_group 0;" ::: "memory");
        __syncthreads();
        if (s + 1 < CNSTEP) conv_load(sb, s + 1, cobase, q0, b, tid);
        mma_step(sb + (uint32_t)(s & 1) * STG, wm, wn, lane, f);
    }

    // epilogue: BN + sigmoid gate; pi -> (r,c); guarded stores
    int head = (cobase >> 6) + wm;
    int qb = q0 + wn * 64;
    float inv = rsqrtf(1.0f + BN_EPS);

    // per-nt attn + validity (independent of mt)
    float av[8][2];
    int hwv[8][2];
    #pragma unroll
    for (int nt = 0; nt < 8; nt++) {
        #pragma unroll
        for (int e = 0; e < 2; e++) {
            int qq = qb + nt * 8 + (lane & 3) * 2 + e;
            int pr = qq / 41, pc = qq - pr * 41;
            bool ok = (pc < 40 && pr < 40);
            int hw = pr * 40 + pc;
            hwv[nt][e] = ok ? hw : -1;
            av[nt][e] = ok ? attn_buf[(size_t)(b * NH + head) * HW + hw] : 0.f;
        }
    }
    #pragma unroll
    for (int mt = 0; mt < 4; mt++) {
        int r0 = cobase + wm * 64 + mt * 16 + (lane >> 2);
        float sc0 = gamma_p[r0] * inv,     bt0 = beta_p[r0];
        float sc8 = gamma_p[r0 + 8] * inv, bt8 = beta_p[r0 + 8];
        #pragma unroll
        for (int nt = 0; nt < 8; nt++) {
            #pragma unroll
            for (int e = 0; e < 2; e++) {
                int hw = hwv[nt][e];
                if (hw >= 0) {
                    out[((size_t)(b * COUT + r0)) * HW + hw]     = (f.acc[mt][nt][e]     * sc0 + bt0) * av[nt][e];
                    out[((size_t)(b * COUT + r0 + 8)) * HW + hw] = (f.acc[mt][nt][e + 2] * sc8 + bt8) * av[nt][e];
                }
            }
        }
    }
}

// ------- embed 1x1 conv (M=256=all E) + fused attn ---------------------------
#define ENSTEP 8
#define TS 260                           // tile row stride in floats
#define G_OFF (128 * TS)                 // g region offset (floats)
#define ESMEM 215040                     // 128*260*4 + 80*256*4

__device__ __forceinline__ void embed_load(uint32_t sb, int s, int q0, int b, int tid) {
    uint32_t st = sb + (uint32_t)(s & 1) * STG;
    const char* a_src = (const char*)(we_h + s * 64);
    size_t xoff = ((size_t)b * PBUF + XOFF + q0) * CIN + s * 64;
    ld_step(st, a_src, (const char*)(xp_hi + xoff), tid);
}

__global__ void __launch_bounds__(256, 1)
embed_attn(const float* __restrict__ gamma_e,
           const float* __restrict__ beta_e,
           const float* __restrict__ head_bias) {
    extern __shared__ __align__(1024) char smem[];
    uint32_t sb = smem_u32(smem);
    int tid = threadIdx.x, wid = tid >> 5, lane = tid & 31;
    int q0 = blockIdx.x * 128;
    int b  = blockIdx.z;
    int wm = wid >> 1, wn = wid & 1;

    Frag f;
    frag_zero(f);

    embed_load(sb, 0, q0, b, tid);
    for (int s = 0; s < ENSTEP; s++) {
        asm volatile("cp.async.wait_group 0;" ::: "memory");
        __syncthreads();
        if (s + 1 < ENSTEP) embed_load(sb, s + 1, q0, b, tid);
        mma_step(sb + (uint32_t)(s & 1) * STG, wm, wn, lane, f);
    }
    __syncthreads();   // stage buffers reused as tile below

    // BN + transpose into tile[q][e]
    float* tile = reinterpret_cast<float*>(smem);
    float inv = rsqrtf(1.0f + BN_EPS);
    #pragma unroll
    for (int mt = 0; mt < 4; mt++) {
        int er = wm * 64 + mt * 16 + (lane >> 2);
        float sc0 = gamma_e[er] * inv,     bt0 = beta_e[er];
        float sc8 = gamma_e[er + 8] * inv, bt8 = beta_e[er + 8];
        #pragma unroll
        for (int nt = 0; nt < 8; nt++) {
            int ql = wn * 64 + nt * 8 + (lane & 3) * 2;
            tile[ql * TS + er]           = f.acc[mt][nt][0] * sc0 + bt0;
            tile[(ql + 1) * TS + er]     = f.acc[mt][nt][1] * sc0 + bt0;
            tile[ql * TS + er + 8]       = f.acc[mt][nt][2] * sc8 + bt8;
            tile[(ql + 1) * TS + er + 8] = f.acc[mt][nt][3] * sc8 + bt8;
        }
    }
    // stage g[b]: 80 x 256 floats
    float* gsm = tile + G_OFF;
    const float* gsrc = g_buf + (size_t)b * NTOK * EE;
    for (int i = tid; i < NTOK * EE / 4; i += 256)
        reinterpret_cast<float4*>(gsm)[i] = reinterpret_cast<const float4*>(gsrc)[i];
    __syncthreads();

    // attn: per thread, q = tid&127, 4 heads
    int q = tid & 127;
    int qq = q0 + q;
    int pr = qq / 41, pc = qq - pr * 41;
    bool valid = (pc < 40 && pr < 40);
    int hw = pr * 40 + pc;
    #pragma unroll
    for (int p = 0; p < 4; p++) {
        int m = (tid >> 7) + p * 2;
        float4 ev[8];
        #pragma unroll
        for (int j = 0; j < 8; j++)
            ev[j] = *reinterpret_cast<const float4*>(&tile[q * TS + m * HC + j * 4]);
        float maxv = -3.4e38f;
        for (int n = 0; n < NTOK; n++) {
            const float4* gp = reinterpret_cast<const float4*>(&gsm[n * EE + m * HC]);
            float acc = 0.f;
            #pragma unroll
            for (int j = 0; j < 8; j++) {
                float4 g4 = gp[j];
                acc += ev[j].x * g4.x + ev[j].y * g4.y + ev[j].z * g4.z + ev[j].w * g4.w;
            }
            maxv = fmaxf(maxv, acc);
        }
        float a = maxv * 0.17677669529663687f + head_bias[m];
        float s = 1.0f / (1.0f + expf(-a));
        if (valid) attn_buf[(size_t)(b * NH + m) * HW + hw] = s;
    }
}

extern "C" void kernel_launch(void* const* d_in, const int* in_sizes, int n_in,
                              void* d_out, int out_size) {
    const float* x         = (const float*)d_in[0];
    const float* guide     = (const float*)d_in[1];
    const float* We        = (const float*)d_in[2];
    const float* gamma_e   = (const float*)d_in[3];
    const float* beta_e    = (const float*)d_in[4];
    const float* Wg        = (const float*)d_in[5];
    const float* bg        = (const float*)d_in[6];
    const float* head_bias = (const float*)d_in[7];
    const float* Wp        = (const float*)d_in[8];
    const float* gamma_p   = (const float*)d_in[9];
    const float* beta_p    = (const float*)d_in[10];
    float* out = (float*)d_out;

    zinit<<<7168, 256>>>();
    guide_gemm<<<dim3(40, 8), 256>>>(guide, Wg, bg);
    wprep<<<512, 256>>>(Wp);
    weprep<<<256, 256>>>(We);
    xprep<<<dim3(40, 8, 16), 256>>>(x);
    cudaFuncSetAttribute(embed_attn, cudaFuncAttributeMaxDynamicSharedMemorySize, ESMEM);
    embed_attn<<<dim3(13, 1, 16), 256, ESMEM>>>(gamma_e, beta_e, head_bias);
    cudaFuncSetAttribute(conv_mma, cudaFuncAttributeMaxDynamicSharedMemorySize, CSMEM);
    conv_mma<<<dim3(13, 2, 16), 256, CSMEM>>>(gamma_p, beta_p, out);
}